// round 10
// baseline (speedup 1.0000x reference)
#include <cuda_runtime.h>
#include <cuda_fp16.h>
#include <cstdint>

#define NPATH 13
#define SMEM_G1 98304
#define SMEM_S2 131072

// ---------------- static device scratch ----------------
__device__ __align__(256) float g_cg[573];
__device__ __align__(256) __half2 g_X[9ull*65536*128];     // slice-major x, (h,h) dup
__device__ __align__(256) __half  g_S[65536ull*6144];      // s[z][pi(48)][w(128)] fp16
__device__ __align__(256) __half  g_W1[1664*256];          // B[group n][k'] (wh,wl) interleaved

// path tables (INS order)
__device__ const int c_L1[NPATH]   = {0,0,0,1,1,1,1,1,2,2,2,2,2};
__device__ const int c_L2[NPATH]   = {0,1,2,0,1,1,2,3,0,1,2,2,3};
__device__ const int c_LO[NPATH]   = {0,1,2,1,0,2,1,2,2,1,0,2,1};
__device__ const int c_CGOFF[NPATH]= {0,1,10,35,44,53,98,143,248,273,318,343,468};
__device__ const int c_YOFF[4]     = {0,1,4,9};
__device__ const int c_WOFF[NPATH] = {0,16384,32768,49152,65536,81920,98304,114688,131072,147456,163840,180224,196608};
__device__ const int c_PIB[NPATH]  = {0,1,2,3,6,9,12,15,18,23,28,33,38};   // cum d1
__device__ const int c_KO[NPATH]   = {0,1,4,1,0,4,1,4,4,1,0,4,1};          // kOut base per path
__device__ const int c_MOFF2[NPATH+1] = {0,1,4,9,18,21,36,45,60,85,100,105,130,145};
// slices (l1, i)
__device__ const int sl_l1[9] = {0,1,1,1,2,2,2,2,2};
__device__ const int sl_i[9]  = {0,0,1,2,0,1,2,3,4};
__device__ const int sl_ntCum[10] = {0,3,8,13,18,23,28,33,38,43};
__device__ const int gOff[3] = {0,384,1024};        // B row offset per l1 group
__device__ const int gPathFirst[3] = {0,3,8};
__device__ const int c_xoff[3] = {0,128,512};
__device__ const int c_d1[3] = {1,3,5};

// ---------------- CG computation (fp64, ported from reference) ----------------
__device__ double dfact(int n){ double r = 1.0; for (int i = 2; i <= n; ++i) r *= (double)i; return r; }

__device__ double su2_cg(int j1,int m1,int j2,int m2,int j3,int m3){
  if (m3 != m1 + m2) return 0.0;
  int vmin = max(max(-j1 + j2 + m3, -j1 + m1), 0);
  int vmax = min(min(j2 + j3 + m1, j3 - j1 + j2), j3 + m3);
  double C = sqrt((double)(2*j3+1) * dfact(j3+j1-j2) * dfact(j3-j1+j2) * dfact(j1+j2-j3)
                  * dfact(j3+m3) * dfact(j3-m3)
                  / (dfact(j1+j2+j3+1) * dfact(j1-m1) * dfact(j1+m1) * dfact(j2-m2) * dfact(j2+m2)));
  double S = 0.0;
  for (int v = vmin; v <= vmax; ++v){
    double sg = ((v + j2 + m2) & 1) ? -1.0 : 1.0;
    S += sg * dfact(j2+j3+m1-v) * dfact(j1-m1+v)
         / (dfact(v) * dfact(j3-j1+j2-v) * dfact(j3+m3-v) * dfact(v+j1-j2-m3));
  }
  return C * S;
}

__device__ void build_q(int l, double (*qr)[7], double (*qi)[7]){
  for (int a = 0; a < 7; ++a) for (int b = 0; b < 7; ++b){ qr[a][b] = 0.0; qi[a][b] = 0.0; }
  double s = 1.0 / sqrt(2.0);
  for (int m = -l; m < 0; ++m){ qr[l+m][l-m] = s; qi[l+m][l+m] = -s; }
  qr[l][l] = 1.0;
  for (int m = 1; m <= l; ++m){
    double sg = (m & 1) ? -1.0 : 1.0;
    qr[l+m][l+m] = sg * s; qi[l+m][l-m] = sg * s;
  }
  int ph = l & 3;
  if (ph){
    for (int a = 0; a < 2*l+1; ++a) for (int b = 0; b < 2*l+1; ++b){
      double re = qr[a][b], im = qi[a][b];
      if (ph == 1){ qr[a][b] =  im; qi[a][b] = -re; }
      else if (ph == 2){ qr[a][b] = -re; qi[a][b] = -im; }
      else { qr[a][b] = -im; qi[a][b] =  re; }
    }
  }
}

__global__ void cg_kernel(){
  int p = threadIdx.x;
  if (p >= NPATH) return;
  int l1 = c_L1[p], l2 = c_L2[p], l3 = c_LO[p];
  int d1 = 2*l1+1, d2 = 2*l2+1, d3 = 2*l3+1;

  double Ccg[5][7][5];
  for (int a = 0; a < 5; ++a) for (int b = 0; b < 7; ++b) for (int c = 0; c < 5; ++c) Ccg[a][b][c] = 0.0;
  for (int m1 = -l1; m1 <= l1; ++m1)
    for (int m2 = -l2; m2 <= l2; ++m2){
      int m3 = m1 + m2;
      if (m3 >= -l3 && m3 <= l3)
        Ccg[l1+m1][l2+m2][l3+m3] = su2_cg(l1, m1, l2, m2, l3, m3);
    }

  double q1r[7][7], q1i[7][7], q2r[7][7], q2i[7][7], q3r[7][7], q3i[7][7];
  build_q(l1, q1r, q1i); build_q(l2, q2r, q2i); build_q(l3, q3r, q3i);

  double outv[5][7][5];
  double norm2 = 0.0;
  for (int j = 0; j < d1; ++j)
    for (int l = 0; l < d2; ++l)
      for (int m = 0; m < d3; ++m){
        double re = 0.0;
        for (int i = 0; i < d1; ++i){
          double a1r = q1r[i][j], a1i = q1i[i][j];
          if (a1r == 0.0 && a1i == 0.0) continue;
          for (int k = 0; k < d2; ++k){
            double a2r = q2r[k][l], a2i = q2i[k][l];
            if (a2r == 0.0 && a2i == 0.0) continue;
            double ar = a1r*a2r - a1i*a2i;
            double ai = a1r*a2i + a1i*a2r;
            for (int n = 0; n < d3; ++n){
              double c = Ccg[i][k][n];
              if (c == 0.0) continue;
              re += c * (ar*q3r[n][m] - ai*(-q3i[n][m]));
            }
          }
        }
        outv[j][l][m] = re;
        norm2 += re * re;
      }
  double cio = (l3 == 0) ? sqrt(1.0/384.0) : (l3 == 1 ? sqrt(3.0/640.0) : sqrt(5.0/640.0));
  double inv = cio / sqrt(norm2);
  for (int j = 0; j < d1; ++j)
    for (int l = 0; l < d2; ++l)
      for (int m = 0; m < d3; ++m)
        g_cg[c_CGOFF[p] + (j*d2 + l)*d3 + m] = (float)(outv[j][l][m] * inv);
}

// ---------------- weight prep: B[group n][k'] = (wh, wl) interleaved ----------------
__global__ void wprep(const float* __restrict__ w){
  int idx = blockIdx.x * 256 + threadIdx.x;
  if (idx >= 1664*128) return;
  int row = idx >> 7, k = idx & 127;   // row = group-n, k = u
  int g = (row < 384) ? 0 : (row < 1024) ? 1 : 2;
  int n = row - gOff[g];
  int pl = n >> 7, wcol = n & 127;
  int p = gPathFirst[g] + pl;
  float v = w[c_WOFF[p] + k*128 + wcol];
  __half h = __float2half_rn(v);
  __half l = __float2half_rn(v - __half2float(h));
  __half2 hl = __halves2half2(h, l);
  *(__half2*)(g_W1 + row*256 + 2*k) = hl;
}

// ---------------- x prep: slice-major fp16 dup ----------------
__global__ void __launch_bounds__(128) xprep(const float* __restrict__ x){
  __shared__ float xr[1152];
  int z = blockIdx.x, t = threadIdx.x;
  for (int j = t; j < 1152; j += 128) xr[j] = x[(size_t)z*1152 + j];
  __syncthreads();
  #pragma unroll
  for (int s = 0; s < 9; ++s){
    int l1 = sl_l1[s], i = sl_i[s], d1 = c_d1[l1];
    float v = xr[c_xoff[l1] + t*d1 + i];
    __half h = __float2half_rn(v);
    g_X[((size_t)s*65536 + z)*128 + t] = __halves2half2(h, h);
  }
}

// ---------------- mma helpers ----------------
__device__ __forceinline__ uint32_t smem_u32(const void* p){
  uint32_t a;
  asm("{ .reg .u64 t; cvta.to.shared.u64 t, %1; cvt.u32.u64 %0, t; }" : "=r"(a) : "l"(p));
  return a;
}
#define SWZ(off) ((off) ^ (((off) >> 3) & 0x70))

__device__ __forceinline__ void cp16(uint32_t dst, const void* src){
  asm volatile("cp.async.cg.shared.global [%0], [%1], 16;" :: "r"(dst), "l"(src) : "memory");
}
__device__ __forceinline__ void cp_commit(){ asm volatile("cp.async.commit_group;" ::: "memory"); }
template<int N> __device__ __forceinline__ void cp_wait(){ asm volatile("cp.async.wait_group %0;" :: "n"(N) : "memory"); }

__device__ __forceinline__ void ldsm4(uint32_t* r, uint32_t addr){
  asm volatile("ldmatrix.sync.aligned.m8n8.x4.shared.b16 {%0,%1,%2,%3}, [%4];"
    : "=r"(r[0]), "=r"(r[1]), "=r"(r[2]), "=r"(r[3]) : "r"(addr));
}
__device__ __forceinline__ void mma16816(float* c, const uint32_t* a, uint32_t b0, uint32_t b1){
  asm volatile("mma.sync.aligned.m16n8k16.row.col.f32.f16.f16.f32 "
    "{%0,%1,%2,%3}, {%4,%5,%6,%7}, {%8,%9}, {%0,%1,%2,%3};"
    : "+f"(c[0]), "+f"(c[1]), "+f"(c[2]), "+f"(c[3])
    : "r"(a[0]), "r"(a[1]), "r"(a[2]), "r"(a[3]), "r"(b0), "r"(b1));
}

// ---------------- GEMM1: s = x @ W per (l1,i) slice, 3-stage, 2 CTA/SM ----------------
__global__ void __launch_bounds__(256, 2) gemm1(){
  extern __shared__ __align__(1024) char smem[];
  uint32_t sb = smem_u32(smem);
  int tid = threadIdx.x, wid = tid >> 5, lane = tid & 31;

  int zt = blockIdx.x / 43;
  int q  = blockIdx.x % 43;
  int s = 0;
  while (q >= sl_ntCum[s+1]) ++s;
  int nt = q - sl_ntCum[s];
  int l1 = sl_l1[s];
  int path = gPathFirst[l1] + nt;
  int pi = c_PIB[path] + sl_i[s];
  size_t R0 = ((size_t)s*65536 + (size_t)zt*128);   // A row base
  int z0 = zt * 128;

  const __half* pA = (const __half*)g_X;            // halves: row*256 + k'
  const __half* pB = g_W1 + (size_t)(gOff[l1] + nt*128)*256;

  int m0 = (wid & 3) * 32;
  int n0 = (wid >> 2) * 64;
  int rA = (lane & 7) + (lane & 8);
  int cAb = (lane >> 4) << 4;
  int rB = (lane & 7) + ((lane >> 4) << 3);
  int cBb = ((lane >> 3) & 1) << 4;

  float acc[2][8][4];
  #pragma unroll
  for (int a = 0; a < 2; ++a)
    #pragma unroll
    for (int b = 0; b < 8; ++b)
      #pragma unroll
      for (int c = 0; c < 4; ++c) acc[a][b][c] = 0.f;

  #define ISSUE1(c_) do{                                                    \
    int s_ = (c_) % 3;                                                      \
    uint32_t stA_ = sb + s_*32768u, stB_ = stA_ + 16384u;                   \
    int k0_ = (c_) * 64;                                                    \
    _Pragma("unroll")                                                       \
    for (int i_ = 0; i_ < 4; ++i_){                                         \
      int idx_ = tid + i_*256;                                              \
      int r_ = idx_ >> 3, sg_ = idx_ & 7;                                   \
      cp16(stA_ + SWZ(r_*128 + sg_*16), pA + (R0 + r_)*256 + k0_ + sg_*8);  \
      cp16(stB_ + SWZ(r_*128 + sg_*16), pB + (size_t)r_*256 + k0_ + sg_*8); \
    }                                                                       \
    cp_commit();                                                            \
  }while(0)

  ISSUE1(0); ISSUE1(1);

  for (int c = 0; c < 4; ++c){
    __syncthreads();
    if (c + 2 < 4){ ISSUE1(c + 2); cp_wait<2>(); }
    else if (c + 1 < 4) cp_wait<1>();
    else cp_wait<0>();
    __syncthreads();

    uint32_t stA = sb + (uint32_t)(c % 3)*32768u;
    uint32_t stB = stA + 16384u;
    #pragma unroll
    for (int kk = 0; kk < 4; ++kk){
      int cb = kk*32;
      uint32_t afr[2][4];
      #pragma unroll
      for (int mt = 0; mt < 2; ++mt)
        ldsm4(afr[mt], stA + SWZ((m0 + mt*16 + rA)*128 + cb + cAb));
      uint32_t bfr[4][4];
      #pragma unroll
      for (int bt = 0; bt < 4; ++bt)
        ldsm4(bfr[bt], stB + SWZ((n0 + bt*16 + rB)*128 + cb + cBb));
      #pragma unroll
      for (int mt = 0; mt < 2; ++mt)
        #pragma unroll
        for (int nt2 = 0; nt2 < 8; ++nt2){
          int bt = nt2 >> 1, rp = (nt2 & 1) * 2;
          mma16816(acc[mt][nt2], afr[mt], bfr[bt][rp], bfr[bt][rp+1]);
        }
    }
  }
  __syncthreads();

  float* Csh = (float*)smem;   // [128][132]
  #pragma unroll
  for (int mt = 0; mt < 2; ++mt)
    #pragma unroll
    for (int nt2 = 0; nt2 < 8; ++nt2){
      int r = m0 + mt*16 + (lane >> 2);
      int cc = n0 + nt2*8 + (lane & 3)*2;
      Csh[r*132 + cc]       = acc[mt][nt2][0];
      Csh[r*132 + cc + 1]   = acc[mt][nt2][1];
      Csh[(r+8)*132 + cc]   = acc[mt][nt2][2];
      Csh[(r+8)*132 + cc+1] = acc[mt][nt2][3];
    }
  __syncthreads();

  for (int rr = wid; rr < 128; rr += 8){
    const float* src = Csh + rr*132 + lane*4;
    __half2 h0 = __floats2half2_rn(src[0], src[1]);
    __half2 h1 = __floats2half2_rn(src[2], src[3]);
    uint32_t u0 = *(uint32_t*)&h0, u1 = *(uint32_t*)&h1;
    __half* dst = g_S + ((size_t)(z0 + rr))*6144 + pi*128 + lane*4;
    asm volatile("st.global.v2.b32 [%0], {%1,%2};" :: "l"(dst), "r"(u0), "r"(u1) : "memory");
  }
  #undef ISSUE1
}

// ---------------- step2: per-node out_z = S_z[128x48] @ M_z[48x16] ----------------
__device__ __forceinline__ uint32_t lds_pair(uint32_t sbS, int k, int m){
  uint32_t lo, hi;
  asm("ld.shared.u16 %0, [%1];" : "=r"(lo) : "r"(sbS + k*272 + m*2));
  asm("ld.shared.u16 %0, [%1];" : "=r"(hi) : "r"(sbS + (k+1)*272 + m*2));
  return lo | (hi << 16);
}

__global__ void __launch_bounds__(256) step2(const float* __restrict__ y,
                                             float* __restrict__ out){
  extern __shared__ __align__(1024) char smem[];
  uint32_t sb = smem_u32(smem);
  int tid = threadIdx.x, wid = tid >> 5, lane = tid & 31;

  const int OFF_M = 106496, OFF_YS = 122880, OFF_MAP = 123392, OFF_CG = 125696;
  uint16_t* map = (uint16_t*)(smem + OFF_MAP);
  float* cgs = (float*)(smem + OFF_CG);
  float* ys  = (float*)(smem + OFF_YS);
  int z0 = blockIdx.x * 8;

  for (int o = tid; o < 1152; o += 256){
    int w, k;
    if (o < 128){ w = o; k = 0; }
    else if (o < 512){ int t = o - 128; w = t/3; k = 1 + (t - w*3); }
    else { int t = o - 512; w = t/5; k = 4 + (t - w*5); }
    map[o] = (uint16_t)(w*18 + k);
  }
  for (int j = tid; j < 573; j += 256) cgs[j] = g_cg[j];
  for (int j = tid; j < 128; j += 256) ys[j] = y[(size_t)z0*16 + j];
  __syncthreads();

  size_t z = z0 + wid;
  uint32_t sbS = sb + wid*13312;
  uint32_t sbM = sb + OFF_M + wid*2048;
  const float* yz = ys + wid*16;

  // stage S_z (48 rows x 128 halves, row stride 272B)
  for (int t = lane; t < 768; t += 32){
    int row = t >> 4, c16 = t & 15;
    cp16(sbS + row*272 + c16*16, g_S + z*6144 + row*128 + c16*8);
  }
  cp_commit();

  // zero M region: exactly 16 rows x 112 bytes = 1792 bytes  (R9 bug: was 3584+)
  for (int t = lane; t < 224; t += 32){
    asm volatile("st.shared.u32 [%0], %1;" :: "r"(sbM + t*8), "r"(0u));
    asm volatile("st.shared.u32 [%0], %1;" :: "r"(sbM + t*8 + 4), "r"(0u));
  }
  __syncwarp();

  // fill M entries: M[kOut][pi] = sum_j cg_p[i,j,kq] * y[z,j]
  for (int e = lane; e < 145; e += 32){
    int p = 0;
    while (e >= c_MOFF2[p+1]) ++p;
    int r = e - c_MOFF2[p];
    int lo = c_LO[p], dlo = 2*lo + 1;
    int i = r / dlo, kq = r - i*dlo;
    int l2 = c_L2[p], d2 = 2*l2 + 1;
    const float* cg = cgs + c_CGOFF[p] + i*d2*dlo + kq;
    const float* yp = yz + c_YOFF[l2];
    float sv = 0.f;
    for (int j = 0; j < d2; ++j) sv += cg[j*dlo] * yp[j];
    unsigned short h = __half_as_ushort(__float2half_rn(sv));
    int kOut = c_KO[p] + kq;
    int pi = c_PIB[p] + i;
    asm volatile("st.shared.u16 [%0], %1;" :: "r"(sbM + kOut*112 + pi*2), "h"(h));
  }
  cp_wait<0>();
  __syncwarp();

  // zero padded S rows 43..47 (128 halves each)
  for (int t = lane; t < 320; t += 32){
    int row = 43 + t/64, col = t % 64;
    asm volatile("st.shared.u32 [%0], %1;" :: "r"(sbS + row*272 + col*4), "r"(0u));
  }
  __syncwarp();

  float acc[8][2][4];
  #pragma unroll
  for (int a = 0; a < 8; ++a)
    #pragma unroll
    for (int b = 0; b < 2; ++b)
      #pragma unroll
      for (int c = 0; c < 4; ++c) acc[a][b][c] = 0.f;

  int r4 = lane >> 2, c2 = (lane & 3)*2;
  int nrow = (lane & 7) + ((lane >> 4) << 3);
  int bcol = ((lane >> 3) & 1) * 16;

  #pragma unroll
  for (int kt = 0; kt < 3; ++kt){
    uint32_t bfr[4];
    ldsm4(bfr, sbM + nrow*112 + kt*32 + bcol);
    int k0 = kt*16 + c2;
    #pragma unroll
    for (int mt = 0; mt < 8; ++mt){
      int m = mt*16 + r4;
      uint32_t a[4];
      a[0] = lds_pair(sbS, k0,     m);
      a[1] = lds_pair(sbS, k0,     m + 8);
      a[2] = lds_pair(sbS, k0 + 8, m);
      a[3] = lds_pair(sbS, k0 + 8, m + 8);
      mma16816(acc[mt][0], a, bfr[0], bfr[1]);
      mma16816(acc[mt][1], a, bfr[2], bfr[3]);
    }
  }
  __syncwarp();

  // stage out tile [128][18] f32 (aliases S region)
  #pragma unroll
  for (int mt = 0; mt < 8; ++mt)
    #pragma unroll
    for (int nt = 0; nt < 2; ++nt){
      int m = mt*16 + r4;
      int cc = nt*8 + c2;
      asm volatile("st.shared.v2.f32 [%0], {%1,%2};"
        :: "r"(sbS + (m*18 + cc)*4), "f"(acc[mt][nt][0]), "f"(acc[mt][nt][1]) : "memory");
      asm volatile("st.shared.v2.f32 [%0], {%1,%2};"
        :: "r"(sbS + ((m+8)*18 + cc)*4), "f"(acc[mt][nt][2]), "f"(acc[mt][nt][3]) : "memory");
    }
  __syncwarp();

  const float* Osh = (const float*)(smem + wid*13312);
  size_t ob = z * 1152;
  #pragma unroll
  for (int j = 0; j < 9; ++j){
    int o = (lane + j*32) * 4;
    float4 v;
    v.x = Osh[map[o]];
    v.y = Osh[map[o+1]];
    v.z = Osh[map[o+2]];
    v.w = Osh[map[o+3]];
    *(float4*)(out + ob + o) = v;
  }
}

// ---------------- launch ----------------
extern "C" void kernel_launch(void* const* d_in, const int* in_sizes, int n_in,
                              void* d_out, int out_size){
  const float* x = (const float*)d_in[0];
  const float* y = (const float*)d_in[1];
  const float* w = (const float*)d_in[2];
  float* out = (float*)d_out;
  int n = in_sizes[0] / 1152;   // 65536

  cudaFuncSetAttribute(gemm1, cudaFuncAttributeMaxDynamicSharedMemorySize, SMEM_G1);
  cudaFuncSetAttribute(step2, cudaFuncAttributeMaxDynamicSharedMemorySize, SMEM_S2);

  cg_kernel<<<1, 32>>>();
  wprep<<<(1664*128 + 255)/256, 256>>>(w);
  xprep<<<n, 128>>>(x);
  gemm1<<<(n / 128) * 43, 256, SMEM_G1>>>();
  step2<<<n / 8, 256, SMEM_S2>>>(y, out);
}

// round 11
// speedup vs baseline: 1.0013x; 1.0013x over previous
#include <cuda_runtime.h>
#include <cuda_fp16.h>
#include <cstdint>

#define NPATH 13
#define SMEM_G1 98304
#define SMEM_S2 131072

// ---------------- static device scratch ----------------
__device__ __align__(256) float g_cg[573];
__device__ __align__(256) __half2 g_X[9ull*65536*128];     // slice-major x, (h,h) dup
__device__ __align__(256) __half  g_S[65536ull*6144];      // s[z][pi(48)][w(128)] fp16
__device__ __align__(256) __half  g_W1[1664*256];          // B[group n][k'] (wh,wl) interleaved

// path tables (INS order)
__device__ const int c_L1[NPATH]   = {0,0,0,1,1,1,1,1,2,2,2,2,2};
__device__ const int c_L2[NPATH]   = {0,1,2,0,1,1,2,3,0,1,2,2,3};
__device__ const int c_LO[NPATH]   = {0,1,2,1,0,2,1,2,2,1,0,2,1};
__device__ const int c_CGOFF[NPATH]= {0,1,10,35,44,53,98,143,248,273,318,343,468};
__device__ const int c_YOFF[4]     = {0,1,4,9};
__device__ const int c_WOFF[NPATH] = {0,16384,32768,49152,65536,81920,98304,114688,131072,147456,163840,180224,196608};
__device__ const int c_PIB[NPATH]  = {0,1,2,3,6,9,12,15,18,23,28,33,38};   // cum d1
__device__ const int c_KO[NPATH]   = {0,1,4,1,0,4,1,4,4,1,0,4,1};          // kOut base per path
__device__ const int c_MOFF2[NPATH+1] = {0,1,4,9,18,21,36,45,60,85,100,105,130,145};
// slices (l1, i)
__device__ const int sl_l1[9] = {0,1,1,1,2,2,2,2,2};
__device__ const int sl_i[9]  = {0,0,1,2,0,1,2,3,4};
__device__ const int sl_ntCum[10] = {0,3,8,13,18,23,28,33,38,43};
__device__ const int gOff[3] = {0,384,1024};        // B row offset per l1 group
__device__ const int gPathFirst[3] = {0,3,8};
__device__ const int c_xoff[3] = {0,128,512};
__device__ const int c_d1[3] = {1,3,5};

// ---------------- CG computation (fp64, ported from reference) ----------------
__device__ double dfact(int n){ double r = 1.0; for (int i = 2; i <= n; ++i) r *= (double)i; return r; }

__device__ double su2_cg(int j1,int m1,int j2,int m2,int j3,int m3){
  if (m3 != m1 + m2) return 0.0;
  int vmin = max(max(-j1 + j2 + m3, -j1 + m1), 0);
  int vmax = min(min(j2 + j3 + m1, j3 - j1 + j2), j3 + m3);
  double C = sqrt((double)(2*j3+1) * dfact(j3+j1-j2) * dfact(j3-j1+j2) * dfact(j1+j2-j3)
                  * dfact(j3+m3) * dfact(j3-m3)
                  / (dfact(j1+j2+j3+1) * dfact(j1-m1) * dfact(j1+m1) * dfact(j2-m2) * dfact(j2+m2)));
  double S = 0.0;
  for (int v = vmin; v <= vmax; ++v){
    double sg = ((v + j2 + m2) & 1) ? -1.0 : 1.0;
    S += sg * dfact(j2+j3+m1-v) * dfact(j1-m1+v)
         / (dfact(v) * dfact(j3-j1+j2-v) * dfact(j3+m3-v) * dfact(v+j1-j2-m3));
  }
  return C * S;
}

__device__ void build_q(int l, double (*qr)[7], double (*qi)[7]){
  for (int a = 0; a < 7; ++a) for (int b = 0; b < 7; ++b){ qr[a][b] = 0.0; qi[a][b] = 0.0; }
  double s = 1.0 / sqrt(2.0);
  for (int m = -l; m < 0; ++m){ qr[l+m][l-m] = s; qi[l+m][l+m] = -s; }
  qr[l][l] = 1.0;
  for (int m = 1; m <= l; ++m){
    double sg = (m & 1) ? -1.0 : 1.0;
    qr[l+m][l+m] = sg * s; qi[l+m][l-m] = sg * s;
  }
  int ph = l & 3;
  if (ph){
    for (int a = 0; a < 2*l+1; ++a) for (int b = 0; b < 2*l+1; ++b){
      double re = qr[a][b], im = qi[a][b];
      if (ph == 1){ qr[a][b] =  im; qi[a][b] = -re; }
      else if (ph == 2){ qr[a][b] = -re; qi[a][b] = -im; }
      else { qr[a][b] = -im; qi[a][b] =  re; }
    }
  }
}

__global__ void cg_kernel(){
  int p = threadIdx.x;
  if (p >= NPATH) return;
  int l1 = c_L1[p], l2 = c_L2[p], l3 = c_LO[p];
  int d1 = 2*l1+1, d2 = 2*l2+1, d3 = 2*l3+1;

  double Ccg[5][7][5];
  for (int a = 0; a < 5; ++a) for (int b = 0; b < 7; ++b) for (int c = 0; c < 5; ++c) Ccg[a][b][c] = 0.0;
  for (int m1 = -l1; m1 <= l1; ++m1)
    for (int m2 = -l2; m2 <= l2; ++m2){
      int m3 = m1 + m2;
      if (m3 >= -l3 && m3 <= l3)
        Ccg[l1+m1][l2+m2][l3+m3] = su2_cg(l1, m1, l2, m2, l3, m3);
    }

  double q1r[7][7], q1i[7][7], q2r[7][7], q2i[7][7], q3r[7][7], q3i[7][7];
  build_q(l1, q1r, q1i); build_q(l2, q2r, q2i); build_q(l3, q3r, q3i);

  double outv[5][7][5];
  double norm2 = 0.0;
  for (int j = 0; j < d1; ++j)
    for (int l = 0; l < d2; ++l)
      for (int m = 0; m < d3; ++m){
        double re = 0.0;
        for (int i = 0; i < d1; ++i){
          double a1r = q1r[i][j], a1i = q1i[i][j];
          if (a1r == 0.0 && a1i == 0.0) continue;
          for (int k = 0; k < d2; ++k){
            double a2r = q2r[k][l], a2i = q2i[k][l];
            if (a2r == 0.0 && a2i == 0.0) continue;
            double ar = a1r*a2r - a1i*a2i;
            double ai = a1r*a2i + a1i*a2r;
            for (int n = 0; n < d3; ++n){
              double c = Ccg[i][k][n];
              if (c == 0.0) continue;
              re += c * (ar*q3r[n][m] - ai*(-q3i[n][m]));
            }
          }
        }
        outv[j][l][m] = re;
        norm2 += re * re;
      }
  double cio = (l3 == 0) ? sqrt(1.0/384.0) : (l3 == 1 ? sqrt(3.0/640.0) : sqrt(5.0/640.0));
  double inv = cio / sqrt(norm2);
  for (int j = 0; j < d1; ++j)
    for (int l = 0; l < d2; ++l)
      for (int m = 0; m < d3; ++m)
        g_cg[c_CGOFF[p] + (j*d2 + l)*d3 + m] = (float)(outv[j][l][m] * inv);
}

// ---------------- weight prep: B[group n][k'] = (wh, wl) interleaved ----------------
__global__ void wprep(const float* __restrict__ w){
  int idx = blockIdx.x * 256 + threadIdx.x;
  if (idx >= 1664*128) return;
  int row = idx >> 7, k = idx & 127;   // row = group-n, k = u
  int g = (row < 384) ? 0 : (row < 1024) ? 1 : 2;
  int n = row - gOff[g];
  int pl = n >> 7, wcol = n & 127;
  int p = gPathFirst[g] + pl;
  float v = w[c_WOFF[p] + k*128 + wcol];
  __half h = __float2half_rn(v);
  __half l = __float2half_rn(v - __half2float(h));
  __half2 hl = __halves2half2(h, l);
  *(__half2*)(g_W1 + row*256 + 2*k) = hl;
}

// ---------------- x prep: slice-major fp16 dup ----------------
__global__ void __launch_bounds__(128) xprep(const float* __restrict__ x){
  __shared__ float xr[1152];
  int z = blockIdx.x, t = threadIdx.x;
  for (int j = t; j < 1152; j += 128) xr[j] = x[(size_t)z*1152 + j];
  __syncthreads();
  #pragma unroll
  for (int s = 0; s < 9; ++s){
    int l1 = sl_l1[s], i = sl_i[s], d1 = c_d1[l1];
    float v = xr[c_xoff[l1] + t*d1 + i];
    __half h = __float2half_rn(v);
    g_X[((size_t)s*65536 + z)*128 + t] = __halves2half2(h, h);
  }
}

// ---------------- mma helpers ----------------
__device__ __forceinline__ uint32_t smem_u32(const void* p){
  uint32_t a;
  asm("{ .reg .u64 t; cvta.to.shared.u64 t, %1; cvt.u32.u64 %0, t; }" : "=r"(a) : "l"(p));
  return a;
}
#define SWZ(off) ((off) ^ (((off) >> 3) & 0x70))

__device__ __forceinline__ void cp16(uint32_t dst, const void* src){
  asm volatile("cp.async.cg.shared.global [%0], [%1], 16;" :: "r"(dst), "l"(src) : "memory");
}
__device__ __forceinline__ void cp_commit(){ asm volatile("cp.async.commit_group;" ::: "memory"); }
template<int N> __device__ __forceinline__ void cp_wait(){ asm volatile("cp.async.wait_group %0;" :: "n"(N) : "memory"); }

__device__ __forceinline__ void ldsm4(uint32_t* r, uint32_t addr){
  asm volatile("ldmatrix.sync.aligned.m8n8.x4.shared.b16 {%0,%1,%2,%3}, [%4];"
    : "=r"(r[0]), "=r"(r[1]), "=r"(r[2]), "=r"(r[3]) : "r"(addr));
}
__device__ __forceinline__ void mma16816(float* c, const uint32_t* a, uint32_t b0, uint32_t b1){
  asm volatile("mma.sync.aligned.m16n8k16.row.col.f32.f16.f16.f32 "
    "{%0,%1,%2,%3}, {%4,%5,%6,%7}, {%8,%9}, {%0,%1,%2,%3};"
    : "+f"(c[0]), "+f"(c[1]), "+f"(c[2]), "+f"(c[3])
    : "r"(a[0]), "r"(a[1]), "r"(a[2]), "r"(a[3]), "r"(b0), "r"(b1));
}

// ---------------- GEMM1: s = x @ W per (l1,i) slice, 3-stage, 2 CTA/SM ----------------
__global__ void __launch_bounds__(256, 2) gemm1(){
  extern __shared__ __align__(1024) char smem[];
  uint32_t sb = smem_u32(smem);
  int tid = threadIdx.x, wid = tid >> 5, lane = tid & 31;

  int zt = blockIdx.x / 43;
  int q  = blockIdx.x % 43;
  int s = 0;
  while (q >= sl_ntCum[s+1]) ++s;
  int nt = q - sl_ntCum[s];
  int l1 = sl_l1[s];
  int path = gPathFirst[l1] + nt;
  int pi = c_PIB[path] + sl_i[s];
  size_t R0 = ((size_t)s*65536 + (size_t)zt*128);   // A row base
  int z0 = zt * 128;

  const __half* pA = (const __half*)g_X;            // halves: row*256 + k'
  const __half* pB = g_W1 + (size_t)(gOff[l1] + nt*128)*256;

  int m0 = (wid & 3) * 32;
  int n0 = (wid >> 2) * 64;
  int rA = (lane & 7) + (lane & 8);
  int cAb = (lane >> 4) << 4;
  int rB = (lane & 7) + ((lane >> 4) << 3);
  int cBb = ((lane >> 3) & 1) << 4;

  float acc[2][8][4];
  #pragma unroll
  for (int a = 0; a < 2; ++a)
    #pragma unroll
    for (int b = 0; b < 8; ++b)
      #pragma unroll
      for (int c = 0; c < 4; ++c) acc[a][b][c] = 0.f;

  #define ISSUE1(c_) do{                                                    \
    int s_ = (c_) % 3;                                                      \
    uint32_t stA_ = sb + s_*32768u, stB_ = stA_ + 16384u;                   \
    int k0_ = (c_) * 64;                                                    \
    _Pragma("unroll")                                                       \
    for (int i_ = 0; i_ < 4; ++i_){                                         \
      int idx_ = tid + i_*256;                                              \
      int r_ = idx_ >> 3, sg_ = idx_ & 7;                                   \
      cp16(stA_ + SWZ(r_*128 + sg_*16), pA + (R0 + r_)*256 + k0_ + sg_*8);  \
      cp16(stB_ + SWZ(r_*128 + sg_*16), pB + (size_t)r_*256 + k0_ + sg_*8); \
    }                                                                       \
    cp_commit();                                                            \
  }while(0)

  ISSUE1(0); ISSUE1(1);

  for (int c = 0; c < 4; ++c){
    __syncthreads();
    if (c + 2 < 4){ ISSUE1(c + 2); cp_wait<2>(); }
    else if (c + 1 < 4) cp_wait<1>();
    else cp_wait<0>();
    __syncthreads();

    uint32_t stA = sb + (uint32_t)(c % 3)*32768u;
    uint32_t stB = stA + 16384u;
    #pragma unroll
    for (int kk = 0; kk < 4; ++kk){
      int cb = kk*32;
      uint32_t afr[2][4];
      #pragma unroll
      for (int mt = 0; mt < 2; ++mt)
        ldsm4(afr[mt], stA + SWZ((m0 + mt*16 + rA)*128 + cb + cAb));
      uint32_t bfr[4][4];
      #pragma unroll
      for (int bt = 0; bt < 4; ++bt)
        ldsm4(bfr[bt], stB + SWZ((n0 + bt*16 + rB)*128 + cb + cBb));
      #pragma unroll
      for (int mt = 0; mt < 2; ++mt)
        #pragma unroll
        for (int nt2 = 0; nt2 < 8; ++nt2){
          int bt = nt2 >> 1, rp = (nt2 & 1) * 2;
          mma16816(acc[mt][nt2], afr[mt], bfr[bt][rp], bfr[bt][rp+1]);
        }
    }
  }
  __syncthreads();

  float* Csh = (float*)smem;   // [128][132]
  #pragma unroll
  for (int mt = 0; mt < 2; ++mt)
    #pragma unroll
    for (int nt2 = 0; nt2 < 8; ++nt2){
      int r = m0 + mt*16 + (lane >> 2);
      int cc = n0 + nt2*8 + (lane & 3)*2;
      Csh[r*132 + cc]       = acc[mt][nt2][0];
      Csh[r*132 + cc + 1]   = acc[mt][nt2][1];
      Csh[(r+8)*132 + cc]   = acc[mt][nt2][2];
      Csh[(r+8)*132 + cc+1] = acc[mt][nt2][3];
    }
  __syncthreads();

  for (int rr = wid; rr < 128; rr += 8){
    const float* src = Csh + rr*132 + lane*4;
    __half2 h0 = __floats2half2_rn(src[0], src[1]);
    __half2 h1 = __floats2half2_rn(src[2], src[3]);
    uint32_t u0 = *(uint32_t*)&h0, u1 = *(uint32_t*)&h1;
    __half* dst = g_S + ((size_t)(z0 + rr))*6144 + pi*128 + lane*4;
    asm volatile("st.global.v2.b32 [%0], {%1,%2};" :: "l"(dst), "r"(u0), "r"(u1) : "memory");
  }
  #undef ISSUE1
}

// ---------------- step2: per-node out_z = S_z[128x48] @ M_z[48x16] ----------------
__device__ __forceinline__ uint32_t lds_pair(uint32_t sbS, int k, int m){
  uint32_t lo, hi;
  asm("ld.shared.u16 %0, [%1];" : "=r"(lo) : "r"(sbS + k*272 + m*2));
  asm("ld.shared.u16 %0, [%1];" : "=r"(hi) : "r"(sbS + (k+1)*272 + m*2));
  return lo | (hi << 16);
}

__global__ void __launch_bounds__(256) step2(const float* __restrict__ y,
                                             float* __restrict__ out){
  extern __shared__ __align__(1024) char smem[];
  uint32_t sb = smem_u32(smem);
  int tid = threadIdx.x, wid = tid >> 5, lane = tid & 31;

  const int OFF_M = 106496, OFF_YS = 122880, OFF_MAP = 123392, OFF_CG = 125696;
  uint16_t* map = (uint16_t*)(smem + OFF_MAP);
  float* cgs = (float*)(smem + OFF_CG);
  float* ys  = (float*)(smem + OFF_YS);
  int z0 = blockIdx.x * 8;

  for (int o = tid; o < 1152; o += 256){
    int w, k;
    if (o < 128){ w = o; k = 0; }
    else if (o < 512){ int t = o - 128; w = t/3; k = 1 + (t - w*3); }
    else { int t = o - 512; w = t/5; k = 4 + (t - w*5); }
    map[o] = (uint16_t)(w*18 + k);
  }
  for (int j = tid; j < 573; j += 256) cgs[j] = g_cg[j];
  for (int j = tid; j < 128; j += 256) ys[j] = y[(size_t)z0*16 + j];
  __syncthreads();

  size_t z = z0 + wid;
  uint32_t sbS = sb + wid*13312;
  uint32_t sbM = sb + OFF_M + wid*2048;
  const float* yz = ys + wid*16;

  // stage S_z (48 rows x 128 halves, row stride 272B)
  for (int t = lane; t < 768; t += 32){
    int row = t >> 4, c16 = t & 15;
    cp16(sbS + row*272 + c16*16, g_S + z*6144 + row*128 + c16*8);
  }
  cp_commit();

  // zero M region: exactly 16 rows x 112 bytes = 1792 bytes  (R9 bug: was 3584+)
  for (int t = lane; t < 224; t += 32){
    asm volatile("st.shared.u32 [%0], %1;" :: "r"(sbM + t*8), "r"(0u));
    asm volatile("st.shared.u32 [%0], %1;" :: "r"(sbM + t*8 + 4), "r"(0u));
  }
  __syncwarp();

  // fill M entries: M[kOut][pi] = sum_j cg_p[i,j,kq] * y[z,j]
  for (int e = lane; e < 145; e += 32){
    int p = 0;
    while (e >= c_MOFF2[p+1]) ++p;
    int r = e - c_MOFF2[p];
    int lo = c_LO[p], dlo = 2*lo + 1;
    int i = r / dlo, kq = r - i*dlo;
    int l2 = c_L2[p], d2 = 2*l2 + 1;
    const float* cg = cgs + c_CGOFF[p] + i*d2*dlo + kq;
    const float* yp = yz + c_YOFF[l2];
    float sv = 0.f;
    for (int j = 0; j < d2; ++j) sv += cg[j*dlo] * yp[j];
    unsigned short h = __half_as_ushort(__float2half_rn(sv));
    int kOut = c_KO[p] + kq;
    int pi = c_PIB[p] + i;
    asm volatile("st.shared.u16 [%0], %1;" :: "r"(sbM + kOut*112 + pi*2), "h"(h));
  }
  cp_wait<0>();
  __syncwarp();

  // zero padded S rows 43..47 (128 halves each)
  for (int t = lane; t < 320; t += 32){
    int row = 43 + t/64, col = t % 64;
    asm volatile("st.shared.u32 [%0], %1;" :: "r"(sbS + row*272 + col*4), "r"(0u));
  }
  __syncwarp();

  float acc[8][2][4];
  #pragma unroll
  for (int a = 0; a < 8; ++a)
    #pragma unroll
    for (int b = 0; b < 2; ++b)
      #pragma unroll
      for (int c = 0; c < 4; ++c) acc[a][b][c] = 0.f;

  int r4 = lane >> 2, c2 = (lane & 3)*2;
  int nrow = (lane & 7) + ((lane >> 4) << 3);
  int bcol = ((lane >> 3) & 1) * 16;

  #pragma unroll
  for (int kt = 0; kt < 3; ++kt){
    uint32_t bfr[4];
    ldsm4(bfr, sbM + nrow*112 + kt*32 + bcol);
    int k0 = kt*16 + c2;
    #pragma unroll
    for (int mt = 0; mt < 8; ++mt){
      int m = mt*16 + r4;
      uint32_t a[4];
      a[0] = lds_pair(sbS, k0,     m);
      a[1] = lds_pair(sbS, k0,     m + 8);
      a[2] = lds_pair(sbS, k0 + 8, m);
      a[3] = lds_pair(sbS, k0 + 8, m + 8);
      mma16816(acc[mt][0], a, bfr[0], bfr[1]);
      mma16816(acc[mt][1], a, bfr[2], bfr[3]);
    }
  }
  __syncwarp();

  // stage out tile [128][18] f32 (aliases S region)
  #pragma unroll
  for (int mt = 0; mt < 8; ++mt)
    #pragma unroll
    for (int nt = 0; nt < 2; ++nt){
      int m = mt*16 + r4;
      int cc = nt*8 + c2;
      asm volatile("st.shared.v2.f32 [%0], {%1,%2};"
        :: "r"(sbS + (m*18 + cc)*4), "f"(acc[mt][nt][0]), "f"(acc[mt][nt][1]) : "memory");
      asm volatile("st.shared.v2.f32 [%0], {%1,%2};"
        :: "r"(sbS + ((m+8)*18 + cc)*4), "f"(acc[mt][nt][2]), "f"(acc[mt][nt][3]) : "memory");
    }
  __syncwarp();

  const float* Osh = (const float*)(smem + wid*13312);
  size_t ob = z * 1152;
  #pragma unroll
  for (int j = 0; j < 9; ++j){
    int o = (lane + j*32) * 4;
    float4 v;
    v.x = Osh[map[o]];
    v.y = Osh[map[o+1]];
    v.z = Osh[map[o+2]];
    v.w = Osh[map[o+3]];
    *(float4*)(out + ob + o) = v;
  }
}

// ---------------- launch ----------------
extern "C" void kernel_launch(void* const* d_in, const int* in_sizes, int n_in,
                              void* d_out, int out_size){
  const float* x = (const float*)d_in[0];
  const float* y = (const float*)d_in[1];
  const float* w = (const float*)d_in[2];
  float* out = (float*)d_out;
  int n = in_sizes[0] / 1152;   // 65536

  cudaFuncSetAttribute(gemm1, cudaFuncAttributeMaxDynamicSharedMemorySize, SMEM_G1);
  cudaFuncSetAttribute(step2, cudaFuncAttributeMaxDynamicSharedMemorySize, SMEM_S2);

  cg_kernel<<<1, 32>>>();
  wprep<<<(1664*128 + 255)/256, 256>>>(w);
  xprep<<<n, 128>>>(x);
  gemm1<<<(n / 128) * 43, 256, SMEM_G1>>>();
  step2<<<n / 8, 256, SMEM_S2>>>(y, out);
}

// round 12
// speedup vs baseline: 1.1046x; 1.1031x over previous
#include <cuda_runtime.h>
#include <cuda_fp16.h>
#include <cstdint>

#define NPATH 13
#define SMEM_G1 98304
#define SMEM_S2 131072

// ---------------- static device scratch ----------------
__device__ __align__(256) float g_cg[573];
__device__ __align__(256) __half g_X[9ull*65536*128];      // slice-major x fp16
__device__ __align__(256) __half g_S[65536ull*6144];       // s[z][pi(48)][w(128)] fp16
__device__ __align__(256) __half g_W1[1664*128];           // B[group n][u] fp16

// path tables (INS order)
__device__ const int c_L1[NPATH]   = {0,0,0,1,1,1,1,1,2,2,2,2,2};
__device__ const int c_L2[NPATH]   = {0,1,2,0,1,1,2,3,0,1,2,2,3};
__device__ const int c_LO[NPATH]   = {0,1,2,1,0,2,1,2,2,1,0,2,1};
__device__ const int c_CGOFF[NPATH]= {0,1,10,35,44,53,98,143,248,273,318,343,468};
__device__ const int c_YOFF[4]     = {0,1,4,9};
__device__ const int c_WOFF[NPATH] = {0,16384,32768,49152,65536,81920,98304,114688,131072,147456,163840,180224,196608};
__device__ const int c_PIB[NPATH]  = {0,1,2,3,6,9,12,15,18,23,28,33,38};   // cum d1
__device__ const int c_KO[NPATH]   = {0,1,4,1,0,4,1,4,4,1,0,4,1};          // kOut base per path
__device__ const int c_MOFF2[NPATH+1] = {0,1,4,9,18,21,36,45,60,85,100,105,130,145};
// slices (l1, i)
__device__ const int sl_l1[9] = {0,1,1,1,2,2,2,2,2};
__device__ const int sl_i[9]  = {0,0,1,2,0,1,2,3,4};
__device__ const int sl_ntCum[10] = {0,3,8,13,18,23,28,33,38,43};
__device__ const int gOff[3] = {0,384,1024};        // B row offset per l1 group
__device__ const int gPathFirst[3] = {0,3,8};
__device__ const int c_xoff[3] = {0,128,512};
__device__ const int c_d1[3] = {1,3,5};

// ---------------- CG computation (fp64, ported from reference) ----------------
__device__ double dfact(int n){ double r = 1.0; for (int i = 2; i <= n; ++i) r *= (double)i; return r; }

__device__ double su2_cg(int j1,int m1,int j2,int m2,int j3,int m3){
  if (m3 != m1 + m2) return 0.0;
  int vmin = max(max(-j1 + j2 + m3, -j1 + m1), 0);
  int vmax = min(min(j2 + j3 + m1, j3 - j1 + j2), j3 + m3);
  double C = sqrt((double)(2*j3+1) * dfact(j3+j1-j2) * dfact(j3-j1+j2) * dfact(j1+j2-j3)
                  * dfact(j3+m3) * dfact(j3-m3)
                  / (dfact(j1+j2+j3+1) * dfact(j1-m1) * dfact(j1+m1) * dfact(j2-m2) * dfact(j2+m2)));
  double S = 0.0;
  for (int v = vmin; v <= vmax; ++v){
    double sg = ((v + j2 + m2) & 1) ? -1.0 : 1.0;
    S += sg * dfact(j2+j3+m1-v) * dfact(j1-m1+v)
         / (dfact(v) * dfact(j3-j1+j2-v) * dfact(j3+m3-v) * dfact(v+j1-j2-m3));
  }
  return C * S;
}

__device__ void build_q(int l, double (*qr)[7], double (*qi)[7]){
  for (int a = 0; a < 7; ++a) for (int b = 0; b < 7; ++b){ qr[a][b] = 0.0; qi[a][b] = 0.0; }
  double s = 1.0 / sqrt(2.0);
  for (int m = -l; m < 0; ++m){ qr[l+m][l-m] = s; qi[l+m][l+m] = -s; }
  qr[l][l] = 1.0;
  for (int m = 1; m <= l; ++m){
    double sg = (m & 1) ? -1.0 : 1.0;
    qr[l+m][l+m] = sg * s; qi[l+m][l-m] = sg * s;
  }
  int ph = l & 3;
  if (ph){
    for (int a = 0; a < 2*l+1; ++a) for (int b = 0; b < 2*l+1; ++b){
      double re = qr[a][b], im = qi[a][b];
      if (ph == 1){ qr[a][b] =  im; qi[a][b] = -re; }
      else if (ph == 2){ qr[a][b] = -re; qi[a][b] = -im; }
      else { qr[a][b] = -im; qi[a][b] =  re; }
    }
  }
}

__global__ void cg_kernel(){
  int p = threadIdx.x;
  if (p >= NPATH) return;
  int l1 = c_L1[p], l2 = c_L2[p], l3 = c_LO[p];
  int d1 = 2*l1+1, d2 = 2*l2+1, d3 = 2*l3+1;

  double Ccg[5][7][5];
  for (int a = 0; a < 5; ++a) for (int b = 0; b < 7; ++b) for (int c = 0; c < 5; ++c) Ccg[a][b][c] = 0.0;
  for (int m1 = -l1; m1 <= l1; ++m1)
    for (int m2 = -l2; m2 <= l2; ++m2){
      int m3 = m1 + m2;
      if (m3 >= -l3 && m3 <= l3)
        Ccg[l1+m1][l2+m2][l3+m3] = su2_cg(l1, m1, l2, m2, l3, m3);
    }

  double q1r[7][7], q1i[7][7], q2r[7][7], q2i[7][7], q3r[7][7], q3i[7][7];
  build_q(l1, q1r, q1i); build_q(l2, q2r, q2i); build_q(l3, q3r, q3i);

  double outv[5][7][5];
  double norm2 = 0.0;
  for (int j = 0; j < d1; ++j)
    for (int l = 0; l < d2; ++l)
      for (int m = 0; m < d3; ++m){
        double re = 0.0;
        for (int i = 0; i < d1; ++i){
          double a1r = q1r[i][j], a1i = q1i[i][j];
          if (a1r == 0.0 && a1i == 0.0) continue;
          for (int k = 0; k < d2; ++k){
            double a2r = q2r[k][l], a2i = q2i[k][l];
            if (a2r == 0.0 && a2i == 0.0) continue;
            double ar = a1r*a2r - a1i*a2i;
            double ai = a1r*a2i + a1i*a2r;
            for (int n = 0; n < d3; ++n){
              double c = Ccg[i][k][n];
              if (c == 0.0) continue;
              re += c * (ar*q3r[n][m] - ai*(-q3i[n][m]));
            }
          }
        }
        outv[j][l][m] = re;
        norm2 += re * re;
      }
  double cio = (l3 == 0) ? sqrt(1.0/384.0) : (l3 == 1 ? sqrt(3.0/640.0) : sqrt(5.0/640.0));
  double inv = cio / sqrt(norm2);
  for (int j = 0; j < d1; ++j)
    for (int l = 0; l < d2; ++l)
      for (int m = 0; m < d3; ++m)
        g_cg[c_CGOFF[p] + (j*d2 + l)*d3 + m] = (float)(outv[j][l][m] * inv);
}

// ---------------- weight prep: B[group n][u] fp16 ----------------
__global__ void wprep(const float* __restrict__ w){
  int idx = blockIdx.x * 256 + threadIdx.x;
  if (idx >= 1664*128) return;
  int row = idx >> 7, k = idx & 127;   // row = group-n, k = u
  int g = (row < 384) ? 0 : (row < 1024) ? 1 : 2;
  int n = row - gOff[g];
  int pl = n >> 7, wcol = n & 127;
  int p = gPathFirst[g] + pl;
  float v = w[c_WOFF[p] + k*128 + wcol];
  g_W1[idx] = __float2half_rn(v);
}

// ---------------- x prep: slice-major fp16 ----------------
__global__ void __launch_bounds__(128) xprep(const float* __restrict__ x){
  __shared__ float xr[1152];
  int z = blockIdx.x, t = threadIdx.x;
  for (int j = t; j < 1152; j += 128) xr[j] = x[(size_t)z*1152 + j];
  __syncthreads();
  #pragma unroll
  for (int s = 0; s < 9; ++s){
    int l1 = sl_l1[s], i = sl_i[s], d1 = c_d1[l1];
    float v = xr[c_xoff[l1] + t*d1 + i];
    g_X[((size_t)s*65536 + z)*128 + t] = __float2half_rn(v);
  }
}

// ---------------- mma helpers ----------------
__device__ __forceinline__ uint32_t smem_u32(const void* p){
  uint32_t a;
  asm("{ .reg .u64 t; cvta.to.shared.u64 t, %1; cvt.u32.u64 %0, t; }" : "=r"(a) : "l"(p));
  return a;
}
#define SWZ(off) ((off) ^ (((off) >> 3) & 0x70))

__device__ __forceinline__ void cp16(uint32_t dst, const void* src){
  asm volatile("cp.async.cg.shared.global [%0], [%1], 16;" :: "r"(dst), "l"(src) : "memory");
}
__device__ __forceinline__ void cp_commit(){ asm volatile("cp.async.commit_group;" ::: "memory"); }
template<int N> __device__ __forceinline__ void cp_wait(){ asm volatile("cp.async.wait_group %0;" :: "n"(N) : "memory"); }

__device__ __forceinline__ void ldsm4(uint32_t* r, uint32_t addr){
  asm volatile("ldmatrix.sync.aligned.m8n8.x4.shared.b16 {%0,%1,%2,%3}, [%4];"
    : "=r"(r[0]), "=r"(r[1]), "=r"(r[2]), "=r"(r[3]) : "r"(addr));
}
__device__ __forceinline__ void ldsm4t(uint32_t* r, uint32_t addr){
  asm volatile("ldmatrix.sync.aligned.m8n8.x4.trans.shared.b16 {%0,%1,%2,%3}, [%4];"
    : "=r"(r[0]), "=r"(r[1]), "=r"(r[2]), "=r"(r[3]) : "r"(addr));
}
__device__ __forceinline__ void mma16816(float* c, const uint32_t* a, uint32_t b0, uint32_t b1){
  asm volatile("mma.sync.aligned.m16n8k16.row.col.f32.f16.f16.f32 "
    "{%0,%1,%2,%3}, {%4,%5,%6,%7}, {%8,%9}, {%0,%1,%2,%3};"
    : "+f"(c[0]), "+f"(c[1]), "+f"(c[2]), "+f"(c[3])
    : "r"(a[0]), "r"(a[1]), "r"(a[2]), "r"(a[3]), "r"(b0), "r"(b1));
}

// ---------------- GEMM1: s = x @ W per (l1,i) slice, K=128, 2-stage ----------------
__global__ void __launch_bounds__(256, 2) gemm1(){
  extern __shared__ __align__(1024) char smem[];
  uint32_t sb = smem_u32(smem);
  int tid = threadIdx.x, wid = tid >> 5, lane = tid & 31;

  int zt = blockIdx.x / 43;
  int q  = blockIdx.x % 43;
  int s = 0;
  while (q >= sl_ntCum[s+1]) ++s;
  int nt = q - sl_ntCum[s];
  int l1 = sl_l1[s];
  int path = gPathFirst[l1] + nt;
  int pi = c_PIB[path] + sl_i[s];
  size_t R0 = ((size_t)s*65536 + (size_t)zt*128);   // A row base
  int z0 = zt * 128;

  const __half* pA = g_X;                            // row stride 128 halves
  const __half* pB = g_W1 + (size_t)(gOff[l1] + nt*128)*128;

  int m0 = (wid & 3) * 32;
  int n0 = (wid >> 2) * 64;
  int rA = (lane & 7) + (lane & 8);
  int cAb = (lane >> 4) << 4;
  int rB = (lane & 7) + ((lane >> 4) << 3);
  int cBb = ((lane >> 3) & 1) << 4;

  float acc[2][8][4];
  #pragma unroll
  for (int a = 0; a < 2; ++a)
    #pragma unroll
    for (int b = 0; b < 8; ++b)
      #pragma unroll
      for (int c = 0; c < 4; ++c) acc[a][b][c] = 0.f;

  #define ISSUE1(c_) do{                                                    \
    int s_ = (c_) & 1;                                                      \
    uint32_t stA_ = sb + s_*32768u, stB_ = stA_ + 16384u;                   \
    int k0_ = (c_) * 64;                                                    \
    _Pragma("unroll")                                                       \
    for (int i_ = 0; i_ < 4; ++i_){                                         \
      int idx_ = tid + i_*256;                                              \
      int r_ = idx_ >> 3, sg_ = idx_ & 7;                                   \
      cp16(stA_ + SWZ(r_*128 + sg_*16), pA + (R0 + r_)*128 + k0_ + sg_*8);  \
      cp16(stB_ + SWZ(r_*128 + sg_*16), pB + (size_t)r_*128 + k0_ + sg_*8); \
    }                                                                       \
    cp_commit();                                                            \
  }while(0)

  ISSUE1(0); ISSUE1(1);

  #pragma unroll
  for (int c = 0; c < 2; ++c){
    if (c == 0) cp_wait<1>(); else cp_wait<0>();
    __syncthreads();

    uint32_t stA = sb + (uint32_t)(c & 1)*32768u;
    uint32_t stB = stA + 16384u;
    #pragma unroll
    for (int kk = 0; kk < 4; ++kk){
      int cb = kk*32;
      uint32_t afr[2][4];
      #pragma unroll
      for (int mt = 0; mt < 2; ++mt)
        ldsm4(afr[mt], stA + SWZ((m0 + mt*16 + rA)*128 + cb + cAb));
      uint32_t bfr[4][4];
      #pragma unroll
      for (int bt = 0; bt < 4; ++bt)
        ldsm4(bfr[bt], stB + SWZ((n0 + bt*16 + rB)*128 + cb + cBb));
      #pragma unroll
      for (int mt = 0; mt < 2; ++mt)
        #pragma unroll
        for (int nt2 = 0; nt2 < 8; ++nt2){
          int bt = nt2 >> 1, rp = (nt2 & 1) * 2;
          mma16816(acc[mt][nt2], afr[mt], bfr[bt][rp], bfr[bt][rp+1]);
        }
    }
    __syncthreads();
  }

  float* Csh = (float*)smem;   // [128][132]
  #pragma unroll
  for (int mt = 0; mt < 2; ++mt)
    #pragma unroll
    for (int nt2 = 0; nt2 < 8; ++nt2){
      int r = m0 + mt*16 + (lane >> 2);
      int cc = n0 + nt2*8 + (lane & 3)*2;
      Csh[r*132 + cc]       = acc[mt][nt2][0];
      Csh[r*132 + cc + 1]   = acc[mt][nt2][1];
      Csh[(r+8)*132 + cc]   = acc[mt][nt2][2];
      Csh[(r+8)*132 + cc+1] = acc[mt][nt2][3];
    }
  __syncthreads();

  for (int rr = wid; rr < 128; rr += 8){
    const float* src = Csh + rr*132 + lane*4;
    __half2 h0 = __floats2half2_rn(src[0], src[1]);
    __half2 h1 = __floats2half2_rn(src[2], src[3]);
    uint32_t u0 = *(uint32_t*)&h0, u1 = *(uint32_t*)&h1;
    __half* dst = g_S + ((size_t)(z0 + rr))*6144 + pi*128 + lane*4;
    asm volatile("st.global.v2.b32 [%0], {%1,%2};" :: "l"(dst), "r"(u0), "r"(u1) : "memory");
  }
  #undef ISSUE1
}

// ---------------- step2: per-node out_z = S_z[128x48] @ M_z[48x16] ----------------
__global__ void __launch_bounds__(256) step2(const float* __restrict__ y,
                                             float* __restrict__ out){
  extern __shared__ __align__(1024) char smem[];
  uint32_t sb = smem_u32(smem);
  int tid = threadIdx.x, wid = tid >> 5, lane = tid & 31;

  const int OFF_M = 106496, OFF_YS = 122880, OFF_MAP = 123392, OFF_CG = 125696;
  uint16_t* map = (uint16_t*)(smem + OFF_MAP);
  float* cgs = (float*)(smem + OFF_CG);
  float* ys  = (float*)(smem + OFF_YS);
  int z0 = blockIdx.x * 8;

  for (int o = tid; o < 1152; o += 256){
    int w, k;
    if (o < 128){ w = o; k = 0; }
    else if (o < 512){ int t = o - 128; w = t/3; k = 1 + (t - w*3); }
    else { int t = o - 512; w = t/5; k = 4 + (t - w*5); }
    map[o] = (uint16_t)(w*18 + k);
  }
  for (int j = tid; j < 573; j += 256) cgs[j] = g_cg[j];
  for (int j = tid; j < 128; j += 256) ys[j] = y[(size_t)z0*16 + j];
  __syncthreads();

  size_t z = z0 + wid;
  uint32_t sbS = sb + wid*13312;
  uint32_t sbM = sb + OFF_M + wid*2048;
  const float* yz = ys + wid*16;

  // stage S_z (48 rows x 128 halves, row stride 272B)
  for (int t = lane; t < 768; t += 32){
    int row = t >> 4, c16 = t & 15;
    cp16(sbS + row*272 + c16*16, g_S + z*6144 + row*128 + c16*8);
  }
  cp_commit();

  // zero M region: exactly 16 rows x 112 bytes = 1792 bytes
  for (int t = lane; t < 224; t += 32){
    asm volatile("st.shared.u32 [%0], %1;" :: "r"(sbM + t*8), "r"(0u));
    asm volatile("st.shared.u32 [%0], %1;" :: "r"(sbM + t*8 + 4), "r"(0u));
  }
  __syncwarp();

  // fill M entries: M[kOut][pi] = sum_j cg_p[i,j,kq] * y[z,j]
  for (int e = lane; e < 145; e += 32){
    int p = 0;
    while (e >= c_MOFF2[p+1]) ++p;
    int r = e - c_MOFF2[p];
    int lo = c_LO[p], dlo = 2*lo + 1;
    int i = r / dlo, kq = r - i*dlo;
    int l2 = c_L2[p], d2 = 2*l2 + 1;
    const float* cg = cgs + c_CGOFF[p] + i*d2*dlo + kq;
    const float* yp = yz + c_YOFF[l2];
    float sv = 0.f;
    for (int j = 0; j < d2; ++j) sv += cg[j*dlo] * yp[j];
    unsigned short h = __half_as_ushort(__float2half_rn(sv));
    int kOut = c_KO[p] + kq;
    int pi = c_PIB[p] + i;
    asm volatile("st.shared.u16 [%0], %1;" :: "r"(sbM + kOut*112 + pi*2), "h"(h));
  }
  cp_wait<0>();
  __syncwarp();

  // zero padded S rows 43..47 (128 halves each)
  for (int t = lane; t < 320; t += 32){
    int row = 43 + t/64, col = t % 64;
    asm volatile("st.shared.u32 [%0], %1;" :: "r"(sbS + row*272 + col*4), "r"(0u));
  }
  __syncwarp();

  float acc[8][2][4];
  #pragma unroll
  for (int a = 0; a < 8; ++a)
    #pragma unroll
    for (int b = 0; b < 2; ++b)
      #pragma unroll
      for (int c = 0; c < 4; ++c) acc[a][b][c] = 0.f;

  int r4 = lane >> 2, c2 = (lane & 3)*2;
  int nrow = (lane & 7) + ((lane >> 4) << 3);
  int bcol = ((lane >> 3) & 1) * 16;
  // ldsm.trans A addressing: row = k, col = m (bytes)
  int tRow = (lane & 7) + ((lane >> 4) & 1) * 8;
  int tColB = ((lane >> 3) & 1) * 16;

  #pragma unroll
  for (int kt = 0; kt < 3; ++kt){
    uint32_t bfr[4];
    ldsm4(bfr, sbM + nrow*112 + kt*32 + bcol);
    uint32_t aBase = sbS + (kt*16 + tRow)*272 + tColB;
    #pragma unroll
    for (int mt = 0; mt < 8; ++mt){
      uint32_t a[4];
      ldsm4t(a, aBase + mt*32);
      mma16816(acc[mt][0], a, bfr[0], bfr[1]);
      mma16816(acc[mt][1], a, bfr[2], bfr[3]);
    }
  }
  __syncwarp();

  // stage out tile [128][18] f32 (aliases S region)
  #pragma unroll
  for (int mt = 0; mt < 8; ++mt)
    #pragma unroll
    for (int nt = 0; nt < 2; ++nt){
      int m = mt*16 + r4;
      int cc = nt*8 + c2;
      asm volatile("st.shared.v2.f32 [%0], {%1,%2};"
        :: "r"(sbS + (m*18 + cc)*4), "f"(acc[mt][nt][0]), "f"(acc[mt][nt][1]) : "memory");
      asm volatile("st.shared.v2.f32 [%0], {%1,%2};"
        :: "r"(sbS + ((m+8)*18 + cc)*4), "f"(acc[mt][nt][2]), "f"(acc[mt][nt][3]) : "memory");
    }
  __syncwarp();

  const float* Osh = (const float*)(smem + wid*13312);
  size_t ob = z * 1152;
  #pragma unroll
  for (int j = 0; j < 9; ++j){
    int o = (lane + j*32) * 4;
    ulonglong1 mq = *(const ulonglong1*)(map + o);   // 4 map entries in one LDS.64
    unsigned long long mv = mq.x;
    float4 v;
    v.x = Osh[(int)(mv & 0xffff)];
    v.y = Osh[(int)((mv >> 16) & 0xffff)];
    v.z = Osh[(int)((mv >> 32) & 0xffff)];
    v.w = Osh[(int)((mv >> 48) & 0xffff)];
    *(float4*)(out + ob + o) = v;
  }
}

// ---------------- launch ----------------
extern "C" void kernel_launch(void* const* d_in, const int* in_sizes, int n_in,
                              void* d_out, int out_size){
  const float* x = (const float*)d_in[0];
  const float* y = (const float*)d_in[1];
  const float* w = (const float*)d_in[2];
  float* out = (float*)d_out;
  int n = in_sizes[0] / 1152;   // 65536

  cudaFuncSetAttribute(gemm1, cudaFuncAttributeMaxDynamicSharedMemorySize, SMEM_G1);
  cudaFuncSetAttribute(step2, cudaFuncAttributeMaxDynamicSharedMemorySize, SMEM_S2);

  cg_kernel<<<1, 32>>>();
  wprep<<<(1664*128 + 255)/256, 256>>>(w);
  xprep<<<n, 128>>>(x);
  gemm1<<<(n / 128) * 43, 256, SMEM_G1>>>();
  step2<<<n / 8, 256, SMEM_S2>>>(y, out);
}

// round 13
// speedup vs baseline: 1.1916x; 1.0788x over previous
#include <cuda_runtime.h>
#include <cuda_fp16.h>
#include <cstdint>

#define NPATH 13
#define SMEM_G1 98304
#define SMEM_S2 65536

// ---------------- static device scratch ----------------
__device__ __align__(256) float g_cg[573];
__device__ __align__(256) unsigned short g_map[1152];
__device__ __align__(256) __half g_X[9ull*65536*128];      // slice-major x fp16
__device__ __align__(256) __half g_S[65536ull*6144];       // s[z][pi(48)][w(128)] fp16
__device__ __align__(256) __half g_M[65536ull*896];        // M[z][kOut(16)][pi(56)] fp16 dense
__device__ __align__(256) __half g_W1[1664*128];           // B[group n][u] fp16

// path tables (INS order) — constant memory (LDC)
__constant__ int c_L1[NPATH]   = {0,0,0,1,1,1,1,1,2,2,2,2,2};
__constant__ int c_L2[NPATH]   = {0,1,2,0,1,1,2,3,0,1,2,2,3};
__constant__ int c_LO[NPATH]   = {0,1,2,1,0,2,1,2,2,1,0,2,1};
__constant__ int c_CGOFF[NPATH]= {0,1,10,35,44,53,98,143,248,273,318,343,468};
__constant__ int c_YOFF[4]     = {0,1,4,9};
__constant__ int c_WOFF[NPATH] = {0,16384,32768,49152,65536,81920,98304,114688,131072,147456,163840,180224,196608};
__constant__ int c_PIB[NPATH]  = {0,1,2,3,6,9,12,15,18,23,28,33,38};   // cum d1
__constant__ int c_KO[NPATH]   = {0,1,4,1,0,4,1,4,4,1,0,4,1};          // kOut base per path
__constant__ int c_MOFF2[NPATH+1] = {0,1,4,9,18,21,36,45,60,85,100,105,130,145};
__constant__ int sl_l1[9] = {0,1,1,1,2,2,2,2,2};
__constant__ int sl_i[9]  = {0,0,1,2,0,1,2,3,4};
__constant__ int sl_ntCum[10] = {0,3,8,13,18,23,28,33,38,43};
__constant__ int gOff[3] = {0,384,1024};
__constant__ int gPathFirst[3] = {0,3,8};
__constant__ int c_xoff[3] = {0,128,512};
__constant__ int c_d1[3] = {1,3,5};

// ---------------- CG computation (fp64, ported from reference) ----------------
__device__ double dfact(int n){ double r = 1.0; for (int i = 2; i <= n; ++i) r *= (double)i; return r; }

__device__ double su2_cg(int j1,int m1,int j2,int m2,int j3,int m3){
  if (m3 != m1 + m2) return 0.0;
  int vmin = max(max(-j1 + j2 + m3, -j1 + m1), 0);
  int vmax = min(min(j2 + j3 + m1, j3 - j1 + j2), j3 + m3);
  double C = sqrt((double)(2*j3+1) * dfact(j3+j1-j2) * dfact(j3-j1+j2) * dfact(j1+j2-j3)
                  * dfact(j3+m3) * dfact(j3-m3)
                  / (dfact(j1+j2+j3+1) * dfact(j1-m1) * dfact(j1+m1) * dfact(j2-m2) * dfact(j2+m2)));
  double S = 0.0;
  for (int v = vmin; v <= vmax; ++v){
    double sg = ((v + j2 + m2) & 1) ? -1.0 : 1.0;
    S += sg * dfact(j2+j3+m1-v) * dfact(j1-m1+v)
         / (dfact(v) * dfact(j3-j1+j2-v) * dfact(j3+m3-v) * dfact(v+j1-j2-m3));
  }
  return C * S;
}

__device__ void build_q(int l, double (*qr)[7], double (*qi)[7]){
  for (int a = 0; a < 7; ++a) for (int b = 0; b < 7; ++b){ qr[a][b] = 0.0; qi[a][b] = 0.0; }
  double s = 1.0 / sqrt(2.0);
  for (int m = -l; m < 0; ++m){ qr[l+m][l-m] = s; qi[l+m][l+m] = -s; }
  qr[l][l] = 1.0;
  for (int m = 1; m <= l; ++m){
    double sg = (m & 1) ? -1.0 : 1.0;
    qr[l+m][l+m] = sg * s; qi[l+m][l-m] = sg * s;
  }
  int ph = l & 3;
  if (ph){
    for (int a = 0; a < 2*l+1; ++a) for (int b = 0; b < 2*l+1; ++b){
      double re = qr[a][b], im = qi[a][b];
      if (ph == 1){ qr[a][b] =  im; qi[a][b] = -re; }
      else if (ph == 2){ qr[a][b] = -re; qi[a][b] = -im; }
      else { qr[a][b] = -im; qi[a][b] =  re; }
    }
  }
}

__global__ void cg_kernel(){
  int p = threadIdx.x;
  // build output-gather map (all 32 threads)
  for (int o = p; o < 1152; o += 32){
    int w, k;
    if (o < 128){ w = o; k = 0; }
    else if (o < 512){ int t = o - 128; w = t/3; k = 1 + (t - w*3); }
    else { int t = o - 512; w = t/5; k = 4 + (t - w*5); }
    g_map[o] = (unsigned short)(w*18 + k);
  }
  if (p >= NPATH) return;
  int l1 = c_L1[p], l2 = c_L2[p], l3 = c_LO[p];
  int d1 = 2*l1+1, d2 = 2*l2+1, d3 = 2*l3+1;

  double Ccg[5][7][5];
  for (int a = 0; a < 5; ++a) for (int b = 0; b < 7; ++b) for (int c = 0; c < 5; ++c) Ccg[a][b][c] = 0.0;
  for (int m1 = -l1; m1 <= l1; ++m1)
    for (int m2 = -l2; m2 <= l2; ++m2){
      int m3 = m1 + m2;
      if (m3 >= -l3 && m3 <= l3)
        Ccg[l1+m1][l2+m2][l3+m3] = su2_cg(l1, m1, l2, m2, l3, m3);
    }

  double q1r[7][7], q1i[7][7], q2r[7][7], q2i[7][7], q3r[7][7], q3i[7][7];
  build_q(l1, q1r, q1i); build_q(l2, q2r, q2i); build_q(l3, q3r, q3i);

  double outv[5][7][5];
  double norm2 = 0.0;
  for (int j = 0; j < d1; ++j)
    for (int l = 0; l < d2; ++l)
      for (int m = 0; m < d3; ++m){
        double re = 0.0;
        for (int i = 0; i < d1; ++i){
          double a1r = q1r[i][j], a1i = q1i[i][j];
          if (a1r == 0.0 && a1i == 0.0) continue;
          for (int k = 0; k < d2; ++k){
            double a2r = q2r[k][l], a2i = q2i[k][l];
            if (a2r == 0.0 && a2i == 0.0) continue;
            double ar = a1r*a2r - a1i*a2i;
            double ai = a1r*a2i + a1i*a2r;
            for (int n = 0; n < d3; ++n){
              double c = Ccg[i][k][n];
              if (c == 0.0) continue;
              re += c * (ar*q3r[n][m] - ai*(-q3i[n][m]));
            }
          }
        }
        outv[j][l][m] = re;
        norm2 += re * re;
      }
  double cio = (l3 == 0) ? sqrt(1.0/384.0) : (l3 == 1 ? sqrt(3.0/640.0) : sqrt(5.0/640.0));
  double inv = cio / sqrt(norm2);
  for (int j = 0; j < d1; ++j)
    for (int l = 0; l < d2; ++l)
      for (int m = 0; m < d3; ++m)
        g_cg[c_CGOFF[p] + (j*d2 + l)*d3 + m] = (float)(outv[j][l][m] * inv);
}

// ---------------- weight prep: B[group n][u] fp16 ----------------
__global__ void wprep(const float* __restrict__ w){
  int idx = blockIdx.x * 256 + threadIdx.x;
  if (idx >= 1664*128) return;
  int row = idx >> 7, k = idx & 127;   // row = group-n, k = u
  int g = (row < 384) ? 0 : (row < 1024) ? 1 : 2;
  int n = row - gOff[g];
  int pl = n >> 7, wcol = n & 127;
  int p = gPathFirst[g] + pl;
  float v = w[c_WOFF[p] + k*128 + wcol];
  g_W1[idx] = __float2half_rn(v);
}

// ---------------- x prep: slice-major fp16 ----------------
__global__ void __launch_bounds__(128) xprep(const float* __restrict__ x){
  __shared__ float xr[1152];
  int z = blockIdx.x, t = threadIdx.x;
  for (int j = t; j < 1152; j += 128) xr[j] = x[(size_t)z*1152 + j];
  __syncthreads();
  #pragma unroll
  for (int s = 0; s < 9; ++s){
    int l1 = sl_l1[s], i = sl_i[s], d1 = c_d1[l1];
    float v = xr[c_xoff[l1] + t*d1 + i];
    g_X[((size_t)s*65536 + z)*128 + t] = __float2half_rn(v);
  }
}

// ---------------- M prep: dense M[z][16][56] fp16 ----------------
__global__ void __launch_bounds__(256) mprep(const float* __restrict__ y){
  __shared__ float ys[32*16];
  __shared__ float cgs[573];
  int z0 = blockIdx.x * 32;
  int tid = threadIdx.x;
  for (int j = tid; j < 512; j += 256) ys[j] = y[(size_t)z0*16 + j];
  for (int j = tid; j < 573; j += 256) cgs[j] = g_cg[j];
  __syncthreads();

  // zero 32 nodes x 448 u32
  uint32_t* d32 = (uint32_t*)(g_M + (size_t)z0*896);
  for (int j = tid; j < 14336; j += 256) d32[j] = 0u;
  __syncthreads();

  for (int ea = tid; ea < 32*145; ea += 256){
    int zl = ea / 145, e = ea - zl*145;
    int p = 0;
    while (e >= c_MOFF2[p+1]) ++p;
    int r = e - c_MOFF2[p];
    int lo = c_LO[p], dlo = 2*lo + 1;
    int i = r / dlo, kq = r - i*dlo;
    int l2 = c_L2[p], d2 = 2*l2 + 1;
    const float* cg = cgs + c_CGOFF[p] + i*d2*dlo + kq;
    const float* yp = ys + zl*16 + c_YOFF[l2];
    float sv = 0.f;
    for (int j = 0; j < d2; ++j) sv += cg[j*dlo] * yp[j];
    int kOut = c_KO[p] + kq;
    int pi = c_PIB[p] + i;
    g_M[((size_t)(z0 + zl))*896 + kOut*56 + pi] = __float2half_rn(sv);
  }
}

// ---------------- mma helpers ----------------
__device__ __forceinline__ uint32_t smem_u32(const void* p){
  uint32_t a;
  asm("{ .reg .u64 t; cvta.to.shared.u64 t, %1; cvt.u32.u64 %0, t; }" : "=r"(a) : "l"(p));
  return a;
}
#define SWZ(off) ((off) ^ (((off) >> 3) & 0x70))

__device__ __forceinline__ void cp16(uint32_t dst, const void* src){
  asm volatile("cp.async.cg.shared.global [%0], [%1], 16;" :: "r"(dst), "l"(src) : "memory");
}
__device__ __forceinline__ void cp_commit(){ asm volatile("cp.async.commit_group;" ::: "memory"); }
template<int N> __device__ __forceinline__ void cp_wait(){ asm volatile("cp.async.wait_group %0;" :: "n"(N) : "memory"); }

__device__ __forceinline__ void ldsm4(uint32_t* r, uint32_t addr){
  asm volatile("ldmatrix.sync.aligned.m8n8.x4.shared.b16 {%0,%1,%2,%3}, [%4];"
    : "=r"(r[0]), "=r"(r[1]), "=r"(r[2]), "=r"(r[3]) : "r"(addr));
}
__device__ __forceinline__ void ldsm4t(uint32_t* r, uint32_t addr){
  asm volatile("ldmatrix.sync.aligned.m8n8.x4.trans.shared.b16 {%0,%1,%2,%3}, [%4];"
    : "=r"(r[0]), "=r"(r[1]), "=r"(r[2]), "=r"(r[3]) : "r"(addr));
}
__device__ __forceinline__ void mma16816(float* c, const uint32_t* a, uint32_t b0, uint32_t b1){
  asm volatile("mma.sync.aligned.m16n8k16.row.col.f32.f16.f16.f32 "
    "{%0,%1,%2,%3}, {%4,%5,%6,%7}, {%8,%9}, {%0,%1,%2,%3};"
    : "+f"(c[0]), "+f"(c[1]), "+f"(c[2]), "+f"(c[3])
    : "r"(a[0]), "r"(a[1]), "r"(a[2]), "r"(a[3]), "r"(b0), "r"(b1));
}

// ---------------- GEMM1: s = x @ W per (l1,i) slice, K=128, 2-stage ----------------
__global__ void __launch_bounds__(256, 2) gemm1(){
  extern __shared__ __align__(1024) char smem[];
  uint32_t sb = smem_u32(smem);
  int tid = threadIdx.x, wid = tid >> 5, lane = tid & 31;

  int zt = blockIdx.x / 43;
  int q  = blockIdx.x % 43;
  int s = 0;
  while (q >= sl_ntCum[s+1]) ++s;
  int nt = q - sl_ntCum[s];
  int l1 = sl_l1[s];
  int path = gPathFirst[l1] + nt;
  int pi = c_PIB[path] + sl_i[s];
  size_t R0 = ((size_t)s*65536 + (size_t)zt*128);
  int z0 = zt * 128;

  const __half* pA = g_X;
  const __half* pB = g_W1 + (size_t)(gOff[l1] + nt*128)*128;

  int m0 = (wid & 3) * 32;
  int n0 = (wid >> 2) * 64;
  int rA = (lane & 7) + (lane & 8);
  int cAb = (lane >> 4) << 4;
  int rB = (lane & 7) + ((lane >> 4) << 3);
  int cBb = ((lane >> 3) & 1) << 4;

  float acc[2][8][4];
  #pragma unroll
  for (int a = 0; a < 2; ++a)
    #pragma unroll
    for (int b = 0; b < 8; ++b)
      #pragma unroll
      for (int c = 0; c < 4; ++c) acc[a][b][c] = 0.f;

  #define ISSUE1(c_) do{                                                    \
    int s_ = (c_) & 1;                                                      \
    uint32_t stA_ = sb + s_*32768u, stB_ = stA_ + 16384u;                   \
    int k0_ = (c_) * 64;                                                    \
    _Pragma("unroll")                                                       \
    for (int i_ = 0; i_ < 4; ++i_){                                         \
      int idx_ = tid + i_*256;                                              \
      int r_ = idx_ >> 3, sg_ = idx_ & 7;                                   \
      cp16(stA_ + SWZ(r_*128 + sg_*16), pA + (R0 + r_)*128 + k0_ + sg_*8);  \
      cp16(stB_ + SWZ(r_*128 + sg_*16), pB + (size_t)r_*128 + k0_ + sg_*8); \
    }                                                                       \
    cp_commit();                                                            \
  }while(0)

  ISSUE1(0); ISSUE1(1);

  #pragma unroll
  for (int c = 0; c < 2; ++c){
    if (c == 0) cp_wait<1>(); else cp_wait<0>();
    __syncthreads();

    uint32_t stA = sb + (uint32_t)(c & 1)*32768u;
    uint32_t stB = stA + 16384u;
    #pragma unroll
    for (int kk = 0; kk < 4; ++kk){
      int cb = kk*32;
      uint32_t afr[2][4];
      #pragma unroll
      for (int mt = 0; mt < 2; ++mt)
        ldsm4(afr[mt], stA + SWZ((m0 + mt*16 + rA)*128 + cb + cAb));
      uint32_t bfr[4][4];
      #pragma unroll
      for (int bt = 0; bt < 4; ++bt)
        ldsm4(bfr[bt], stB + SWZ((n0 + bt*16 + rB)*128 + cb + cBb));
      #pragma unroll
      for (int mt = 0; mt < 2; ++mt)
        #pragma unroll
        for (int nt2 = 0; nt2 < 8; ++nt2){
          int bt = nt2 >> 1, rp = (nt2 & 1) * 2;
          mma16816(acc[mt][nt2], afr[mt], bfr[bt][rp], bfr[bt][rp+1]);
        }
    }
    __syncthreads();
  }

  float* Csh = (float*)smem;   // [128][132]
  #pragma unroll
  for (int mt = 0; mt < 2; ++mt)
    #pragma unroll
    for (int nt2 = 0; nt2 < 8; ++nt2){
      int r = m0 + mt*16 + (lane >> 2);
      int cc = n0 + nt2*8 + (lane & 3)*2;
      Csh[r*132 + cc]       = acc[mt][nt2][0];
      Csh[r*132 + cc + 1]   = acc[mt][nt2][1];
      Csh[(r+8)*132 + cc]   = acc[mt][nt2][2];
      Csh[(r+8)*132 + cc+1] = acc[mt][nt2][3];
    }
  __syncthreads();

  for (int rr = wid; rr < 128; rr += 8){
    const float* src = Csh + rr*132 + lane*4;
    __half2 h0 = __floats2half2_rn(src[0], src[1]);
    __half2 h1 = __floats2half2_rn(src[2], src[3]);
    uint32_t u0 = *(uint32_t*)&h0, u1 = *(uint32_t*)&h1;
    __half* dst = g_S + ((size_t)(z0 + rr))*6144 + pi*128 + lane*4;
    asm volatile("st.global.v2.b32 [%0], {%1,%2};" :: "l"(dst), "r"(u0), "r"(u1) : "memory");
  }
  #undef ISSUE1
}

// ---------------- step2: per-node out_z = S_z[128x48] @ M_z[48x16] ----------------
// 128 threads, 4 warps, 4 nodes per CTA; smem 64KB -> 3 CTAs/SM
__global__ void __launch_bounds__(128) step2(float* __restrict__ out){
  extern __shared__ __align__(1024) char smem[];
  uint32_t sb = smem_u32(smem);
  int tid = threadIdx.x, wid = tid >> 5, lane = tid & 31;

  const int OFF_M = 53248, OFF_MAP = 61440;
  int z0 = blockIdx.x * 4;
  size_t z = z0 + wid;
  uint32_t sbS = sb + wid*13312;
  uint32_t sbM = sb + OFF_M + wid*2048;

  // stage map (CTA-wide, 2304B)
  for (int t = tid; t < 144; t += 128)
    cp16(sb + OFF_MAP + t*16, (const char*)g_map + t*16);
  // stage S (per warp, 12288B, rows 272B stride)
  for (int t = lane; t < 768; t += 32){
    int row = t >> 4, c16 = t & 15;
    cp16(sbS + row*272 + c16*16, g_S + z*6144 + row*128 + c16*8);
  }
  // stage M (per warp, 1792B linear; rows naturally 112B)
  for (int t = lane; t < 112; t += 32)
    cp16(sbM + t*16, g_M + z*896 + t*8);
  cp_commit();
  cp_wait<0>();
  __syncthreads();

  // zero padded S rows 43..47 (5 rows x 256B)
  for (int t = lane; t < 160; t += 32){
    int row = 43 + t/32, col = t & 31;
    asm volatile("st.shared.u64 [%0], %1;" :: "r"(sbS + row*272 + col*8), "l"(0ull));
  }
  __syncwarp();

  float acc[8][2][4];
  #pragma unroll
  for (int a = 0; a < 8; ++a)
    #pragma unroll
    for (int b = 0; b < 2; ++b)
      #pragma unroll
      for (int c = 0; c < 4; ++c) acc[a][b][c] = 0.f;

  int r4 = lane >> 2, c2 = (lane & 3)*2;
  int nrow = (lane & 7) + ((lane >> 4) << 3);
  int bcol = ((lane >> 3) & 1) * 16;
  int tRow = (lane & 7) + ((lane >> 4) & 1) * 8;
  int tColB = ((lane >> 3) & 1) * 16;

  #pragma unroll
  for (int kt = 0; kt < 3; ++kt){
    uint32_t bfr[4];
    ldsm4(bfr, sbM + nrow*112 + kt*32 + bcol);
    uint32_t aBase = sbS + (kt*16 + tRow)*272 + tColB;
    #pragma unroll
    for (int mt = 0; mt < 8; ++mt){
      uint32_t a[4];
      ldsm4t(a, aBase + mt*32);
      mma16816(acc[mt][0], a, bfr[0], bfr[1]);
      mma16816(acc[mt][1], a, bfr[2], bfr[3]);
    }
  }
  __syncwarp();

  // stage out tile [128][18] f32 in S region
  #pragma unroll
  for (int mt = 0; mt < 8; ++mt)
    #pragma unroll
    for (int nt = 0; nt < 2; ++nt){
      int m = mt*16 + r4;
      int cc = nt*8 + c2;
      asm volatile("st.shared.v2.f32 [%0], {%1,%2};"
        :: "r"(sbS + (m*18 + cc)*4), "f"(acc[mt][nt][0]), "f"(acc[mt][nt][1]) : "memory");
      asm volatile("st.shared.v2.f32 [%0], {%1,%2};"
        :: "r"(sbS + ((m+8)*18 + cc)*4), "f"(acc[mt][nt][2]), "f"(acc[mt][nt][3]) : "memory");
    }
  __syncwarp();

  const uint16_t* map = (const uint16_t*)(smem + OFF_MAP);
  const float* Osh = (const float*)(smem + wid*13312);
  size_t ob = z * 1152;
  #pragma unroll
  for (int j = 0; j < 9; ++j){
    int o = (lane + j*32) * 4;
    ulonglong1 mq = *(const ulonglong1*)(map + o);
    unsigned long long mv = mq.x;
    float4 v;
    v.x = Osh[(int)(mv & 0xffff)];
    v.y = Osh[(int)((mv >> 16) & 0xffff)];
    v.z = Osh[(int)((mv >> 32) & 0xffff)];
    v.w = Osh[(int)((mv >> 48) & 0xffff)];
    *(float4*)(out + ob + o) = v;
  }
}

// ---------------- launch ----------------
extern "C" void kernel_launch(void* const* d_in, const int* in_sizes, int n_in,
                              void* d_out, int out_size){
  const float* x = (const float*)d_in[0];
  const float* y = (const float*)d_in[1];
  const float* w = (const float*)d_in[2];
  float* out = (float*)d_out;
  int n = in_sizes[0] / 1152;   // 65536

  cudaFuncSetAttribute(gemm1, cudaFuncAttributeMaxDynamicSharedMemorySize, SMEM_G1);
  cudaFuncSetAttribute(step2, cudaFuncAttributeMaxDynamicSharedMemorySize, SMEM_S2);

  cg_kernel<<<1, 32>>>();
  wprep<<<(1664*128 + 255)/256, 256>>>(w);
  xprep<<<n, 128>>>(x);
  mprep<<<n / 32, 256>>>(y);
  gemm1<<<(n / 128) * 43, 256, SMEM_G1>>>();
  step2<<<n / 4, 128, SMEM_S2>>>(out);
}

// round 16
// speedup vs baseline: 1.1988x; 1.0061x over previous
#include <cuda_runtime.h>
#include <cuda_fp16.h>
#include <cstdint>

#define NPATH 13
#define SMEM_G1 98304
#define SMEM_S2 56320

// ---------------- static device scratch ----------------
__device__ __align__(256) float g_cg[573];
__device__ __align__(256) unsigned short g_map[1152];
__device__ __align__(256) __half g_X[9ull*65536*128];      // slice-major x fp16
__device__ __align__(256) __half g_S[65536ull*6144];       // s[z][pi(48)][w(128)] fp16
__device__ __align__(256) __half g_M[65536ull*896];        // M[z][kOut(16)][pi(56)] fp16 dense
__device__ __align__(256) __half g_W1[1664*128];           // B[group n][u] fp16

// path tables — constant memory
__constant__ int c_L1[NPATH]   = {0,0,0,1,1,1,1,1,2,2,2,2,2};
__constant__ int c_L2[NPATH]   = {0,1,2,0,1,1,2,3,0,1,2,2,3};
__constant__ int c_LO[NPATH]   = {0,1,2,1,0,2,1,2,2,1,0,2,1};
__constant__ int c_CGOFF[NPATH]= {0,1,10,35,44,53,98,143,248,273,318,343,468};
__constant__ int c_YOFF[4]     = {0,1,4,9};
__constant__ int c_WOFF[NPATH] = {0,16384,32768,49152,65536,81920,98304,114688,131072,147456,163840,180224,196608};
__constant__ int c_PIB[NPATH]  = {0,1,2,3,6,9,12,15,18,23,28,33,38};
__constant__ int c_KO[NPATH]   = {0,1,4,1,0,4,1,4,4,1,0,4,1};
__constant__ int c_MOFF2[NPATH+1] = {0,1,4,9,18,21,36,45,60,85,100,105,130,145};
__constant__ int sl_l1[9] = {0,1,1,1,2,2,2,2,2};
__constant__ int sl_i[9]  = {0,0,1,2,0,1,2,3,4};
__constant__ int sl_ntCum[10] = {0,3,8,13,18,23,28,33,38,43};
__constant__ int gOff[3] = {0,384,1024};
__constant__ int gPathFirst[3] = {0,3,8};
__constant__ int c_xoff[3] = {0,128,512};
__constant__ int c_d1[3] = {1,3,5};

// ---------------- CG computation (fp64, ported from reference) ----------------
__device__ double dfact(int n){ double r = 1.0; for (int i = 2; i <= n; ++i) r *= (double)i; return r; }

__device__ double su2_cg(int j1,int m1,int j2,int m2,int j3,int m3){
  if (m3 != m1 + m2) return 0.0;
  int vmin = max(max(-j1 + j2 + m3, -j1 + m1), 0);
  int vmax = min(min(j2 + j3 + m1, j3 - j1 + j2), j3 + m3);
  double C = sqrt((double)(2*j3+1) * dfact(j3+j1-j2) * dfact(j3-j1+j2) * dfact(j1+j2-j3)
                  * dfact(j3+m3) * dfact(j3-m3)
                  / (dfact(j1+j2+j3+1) * dfact(j1-m1) * dfact(j1+m1) * dfact(j2-m2) * dfact(j2+m2)));
  double S = 0.0;
  for (int v = vmin; v <= vmax; ++v){
    double sg = ((v + j2 + m2) & 1) ? -1.0 : 1.0;
    S += sg * dfact(j2+j3+m1-v) * dfact(j1-m1+v)
         / (dfact(v) * dfact(j3-j1+j2-v) * dfact(j3+m3-v) * dfact(v+j1-j2-m3));
  }
  return C * S;
}

__device__ void build_q(int l, double (*qr)[7], double (*qi)[7]){
  for (int a = 0; a < 7; ++a) for (int b = 0; b < 7; ++b){ qr[a][b] = 0.0; qi[a][b] = 0.0; }
  double s = 1.0 / sqrt(2.0);
  for (int m = -l; m < 0; ++m){ qr[l+m][l-m] = s; qi[l+m][l+m] = -s; }
  qr[l][l] = 1.0;
  for (int m = 1; m <= l; ++m){
    double sg = (m & 1) ? -1.0 : 1.0;
    qr[l+m][l+m] = sg * s; qi[l+m][l-m] = sg * s;
  }
  int ph = l & 3;
  if (ph){
    for (int a = 0; a < 2*l+1; ++a) for (int b = 0; b < 2*l+1; ++b){
      double re = qr[a][b], im = qi[a][b];
      if (ph == 1){ qr[a][b] =  im; qi[a][b] = -re; }
      else if (ph == 2){ qr[a][b] = -re; qi[a][b] = -im; }
      else { qr[a][b] = -im; qi[a][b] =  re; }
    }
  }
}

__global__ void cg_kernel(){
  int p = threadIdx.x;
  for (int o = p; o < 1152; o += 32){
    int w, k;
    if (o < 128){ w = o; k = 0; }
    else if (o < 512){ int t = o - 128; w = t/3; k = 1 + (t - w*3); }
    else { int t = o - 512; w = t/5; k = 4 + (t - w*5); }
    g_map[o] = (unsigned short)(w*18 + k);
  }
  if (p >= NPATH) return;
  int l1 = c_L1[p], l2 = c_L2[p], l3 = c_LO[p];
  int d1 = 2*l1+1, d2 = 2*l2+1, d3 = 2*l3+1;

  double Ccg[5][7][5];
  for (int a = 0; a < 5; ++a) for (int b = 0; b < 7; ++b) for (int c = 0; c < 5; ++c) Ccg[a][b][c] = 0.0;
  for (int m1 = -l1; m1 <= l1; ++m1)
    for (int m2 = -l2; m2 <= l2; ++m2){
      int m3 = m1 + m2;
      if (m3 >= -l3 && m3 <= l3)
        Ccg[l1+m1][l2+m2][l3+m3] = su2_cg(l1, m1, l2, m2, l3, m3);
    }

  double q1r[7][7], q1i[7][7], q2r[7][7], q2i[7][7], q3r[7][7], q3i[7][7];
  build_q(l1, q1r, q1i); build_q(l2, q2r, q2i); build_q(l3, q3r, q3i);

  double outv[5][7][5];
  double norm2 = 0.0;
  for (int j = 0; j < d1; ++j)
    for (int l = 0; l < d2; ++l)
      for (int m = 0; m < d3; ++m){
        double re = 0.0;
        for (int i = 0; i < d1; ++i){
          double a1r = q1r[i][j], a1i = q1i[i][j];
          if (a1r == 0.0 && a1i == 0.0) continue;
          for (int k = 0; k < d2; ++k){
            double a2r = q2r[k][l], a2i = q2i[k][l];
            if (a2r == 0.0 && a2i == 0.0) continue;
            double ar = a1r*a2r - a1i*a2i;
            double ai = a1r*a2i + a1i*a2r;
            for (int n = 0; n < d3; ++n){
              double c = Ccg[i][k][n];
              if (c == 0.0) continue;
              re += c * (ar*q3r[n][m] - ai*(-q3i[n][m]));
            }
          }
        }
        outv[j][l][m] = re;
        norm2 += re * re;
      }
  double cio = (l3 == 0) ? sqrt(1.0/384.0) : (l3 == 1 ? sqrt(3.0/640.0) : sqrt(5.0/640.0));
  double inv = cio / sqrt(norm2);
  for (int j = 0; j < d1; ++j)
    for (int l = 0; l < d2; ++l)
      for (int m = 0; m < d3; ++m)
        g_cg[c_CGOFF[p] + (j*d2 + l)*d3 + m] = (float)(outv[j][l][m] * inv);
}

// ---------------- weight prep ----------------
__global__ void wprep(const float* __restrict__ w){
  int idx = blockIdx.x * 256 + threadIdx.x;
  if (idx >= 1664*128) return;
  int row = idx >> 7, k = idx & 127;
  int g = (row < 384) ? 0 : (row < 1024) ? 1 : 2;
  int n = row - gOff[g];
  int pl = n >> 7, wcol = n & 127;
  int p = gPathFirst[g] + pl;
  g_W1[idx] = __float2half_rn(w[c_WOFF[p] + k*128 + wcol]);
}

// ---------------- x prep: 4 nodes/CTA, half2 stores ----------------
__global__ void __launch_bounds__(256) xprep(const float* __restrict__ x){
  __shared__ float xr[4*1152];
  int z0 = blockIdx.x * 4, tid = threadIdx.x;
  for (int j = tid; j < 4608; j += 256) xr[j] = x[(size_t)z0*1152 + j];
  __syncthreads();
  int zl = tid >> 6, up = tid & 63;
  const float* xz = xr + zl*1152;
  size_t zrow = z0 + zl;
  #pragma unroll
  for (int s = 0; s < 9; ++s){
    int l1 = sl_l1[s], i = sl_i[s], d1 = c_d1[l1];
    const float* b = xz + c_xoff[l1] + i;
    float v0 = b[(2*up)*d1], v1 = b[(2*up+1)*d1];
    *(__half2*)(g_X + ((size_t)s*65536 + zrow)*128 + 2*up) = __floats2half2_rn(v0, v1);
  }
}

// ---------------- M prep: dense M[z][16][56] fp16 ----------------
__global__ void __launch_bounds__(256) mprep(const float* __restrict__ y){
  __shared__ float ys[32*16];
  __shared__ float cgs[573];
  int z0 = blockIdx.x * 32;
  int tid = threadIdx.x;
  for (int j = tid; j < 512; j += 256) ys[j] = y[(size_t)z0*16 + j];
  for (int j = tid; j < 573; j += 256) cgs[j] = g_cg[j];
  __syncthreads();

  uint32_t* d32 = (uint32_t*)(g_M + (size_t)z0*896);
  for (int j = tid; j < 14336; j += 256) d32[j] = 0u;
  __syncthreads();

  for (int ea = tid; ea < 32*145; ea += 256){
    int zl = ea / 145, e = ea - zl*145;
    int p = 0;
    while (e >= c_MOFF2[p+1]) ++p;
    int r = e - c_MOFF2[p];
    int lo = c_LO[p], dlo = 2*lo + 1;
    int i = r / dlo, kq = r - i*dlo;
    int l2 = c_L2[p], d2 = 2*l2 + 1;
    const float* cg = cgs + c_CGOFF[p] + i*d2*dlo + kq;
    const float* yp = ys + zl*16 + c_YOFF[l2];
    float sv = 0.f;
    for (int j = 0; j < d2; ++j) sv += cg[j*dlo] * yp[j];
    g_M[((size_t)(z0 + zl))*896 + (c_KO[p] + kq)*56 + (c_PIB[p] + i)] = __float2half_rn(sv);
  }
}

// ---------------- mma helpers ----------------
__device__ __forceinline__ uint32_t smem_u32(const void* p){
  uint32_t a;
  asm("{ .reg .u64 t; cvta.to.shared.u64 t, %1; cvt.u32.u64 %0, t; }" : "=r"(a) : "l"(p));
  return a;
}
#define SWZ(off) ((off) ^ (((off) >> 3) & 0x70))
// S-tile swizzle: 256B rows, 16B blocks; block index XOR (row & 7)
#define SWZ2(row, colblk) ((row)*256 + ((((colblk) ^ ((row) & 7))) << 4))

__device__ __forceinline__ void cp16(uint32_t dst, const void* src){
  asm volatile("cp.async.cg.shared.global [%0], [%1], 16;" :: "r"(dst), "l"(src) : "memory");
}
__device__ __forceinline__ void cp_commit(){ asm volatile("cp.async.commit_group;" ::: "memory"); }
template<int N> __device__ __forceinline__ void cp_wait(){ asm volatile("cp.async.wait_group %0;" :: "n"(N) : "memory"); }

__device__ __forceinline__ void ldsm4(uint32_t* r, uint32_t addr){
  asm volatile("ldmatrix.sync.aligned.m8n8.x4.shared.b16 {%0,%1,%2,%3}, [%4];"
    : "=r"(r[0]), "=r"(r[1]), "=r"(r[2]), "=r"(r[3]) : "r"(addr));
}
__device__ __forceinline__ void ldsm4t(uint32_t* r, uint32_t addr){
  asm volatile("ldmatrix.sync.aligned.m8n8.x4.trans.shared.b16 {%0,%1,%2,%3}, [%4];"
    : "=r"(r[0]), "=r"(r[1]), "=r"(r[2]), "=r"(r[3]) : "r"(addr));
}
__device__ __forceinline__ void mma16816(float* c, const uint32_t* a, uint32_t b0, uint32_t b1){
  asm volatile("mma.sync.aligned.m16n8k16.row.col.f32.f16.f16.f32 "
    "{%0,%1,%2,%3}, {%4,%5,%6,%7}, {%8,%9}, {%0,%1,%2,%3};"
    : "+f"(c[0]), "+f"(c[1]), "+f"(c[2]), "+f"(c[3])
    : "r"(a[0]), "r"(a[1]), "r"(a[2]), "r"(a[3]), "r"(b0), "r"(b1));
}

// ---------------- GEMM1 v2: B pinned in smem, 8 zt per CTA, dbl-buffered A ----------------
__global__ void __launch_bounds__(256, 2) gemm1(){
  extern __shared__ __align__(1024) char smem[];
  uint32_t sb = smem_u32(smem);
  int tid = threadIdx.x, wid = tid >> 5, lane = tid & 31;

  int chunk = blockIdx.x / 43;
  int q     = blockIdx.x % 43;
  int s = 0;
  while (q >= sl_ntCum[s+1]) ++s;
  int nt = q - sl_ntCum[s];
  int l1 = sl_l1[s];
  int path = gPathFirst[l1] + nt;
  int pi = c_PIB[path] + sl_i[s];

  const __half* pA = g_X + ((size_t)s*65536)*128;
  const __half* pB = g_W1 + (size_t)(gOff[l1] + nt*128)*128;

  int m0 = (wid & 3) * 32;
  int n0 = (wid >> 2) * 64;
  int rA = (lane & 7) + (lane & 8);
  int cAb = (lane >> 4) << 4;
  int rB = (lane & 7) + ((lane >> 4) << 3);
  int cBb = ((lane >> 3) & 1) << 4;

  // stage B once (two 16K k-halves)
  {
    #pragma unroll
    for (int i = 0; i < 4; ++i){
      int idx = tid + i*256;
      int r = idx >> 3, sg = idx & 7;
      uint32_t d = SWZ(r*128 + sg*16);
      cp16(sb + d,          pB + (size_t)r*128 + sg*8);
      cp16(sb + 16384 + d,  pB + (size_t)r*128 + 64 + sg*8);
    }
    cp_commit();
  }

  #define ISSUE_A(it_) do{                                                   \
    uint32_t bufA_ = sb + 32768u + (uint32_t)((it_) & 1)*32768u;              \
    size_t R0_ = ((size_t)chunk*8 + (it_))*128;                               \
    _Pragma("unroll")                                                         \
    for (int i_ = 0; i_ < 4; ++i_){                                           \
      int idx_ = tid + i_*256;                                                \
      int r_ = idx_ >> 3, sg_ = idx_ & 7;                                     \
      uint32_t d_ = SWZ(r_*128 + sg_*16);                                     \
      cp16(bufA_ + d_,          pA + (R0_ + r_)*128 + sg_*8);                 \
      cp16(bufA_ + 16384u + d_, pA + (R0_ + r_)*128 + 64 + sg_*8);            \
    }                                                                         \
    cp_commit();                                                              \
  }while(0)

  ISSUE_A(0);

  for (int it = 0; it < 8; ++it){
    if (it + 1 < 8){ ISSUE_A(it + 1); cp_wait<1>(); }
    else cp_wait<0>();
    __syncthreads();

    float acc[2][8][4];
    #pragma unroll
    for (int a = 0; a < 2; ++a)
      #pragma unroll
      for (int b = 0; b < 8; ++b)
        #pragma unroll
        for (int c = 0; c < 4; ++c) acc[a][b][c] = 0.f;

    uint32_t bufA = sb + 32768u + (uint32_t)(it & 1)*32768u;
    #pragma unroll
    for (int kk = 0; kk < 8; ++kk){
      uint32_t stA = bufA + (uint32_t)(kk >> 2)*16384u;
      uint32_t stB = sb   + (uint32_t)(kk >> 2)*16384u;
      int cb = (kk & 3)*32;
      uint32_t afr[2][4];
      #pragma unroll
      for (int mt = 0; mt < 2; ++mt)
        ldsm4(afr[mt], stA + SWZ((m0 + mt*16 + rA)*128 + cb + cAb));
      uint32_t bfr[4][4];
      #pragma unroll
      for (int bt = 0; bt < 4; ++bt)
        ldsm4(bfr[bt], stB + SWZ((n0 + bt*16 + rB)*128 + cb + cBb));
      #pragma unroll
      for (int mt = 0; mt < 2; ++mt)
        #pragma unroll
        for (int nt2 = 0; nt2 < 8; ++nt2){
          int bt = nt2 >> 1, rp = (nt2 & 1) * 2;
          mma16816(acc[mt][nt2], afr[mt], bfr[bt][rp], bfr[bt][rp+1]);
        }
    }

    int z0 = (chunk*8 + it) * 128;
    #pragma unroll
    for (int mt = 0; mt < 2; ++mt)
      #pragma unroll
      for (int nt2 = 0; nt2 < 8; ++nt2){
        int r = m0 + mt*16 + (lane >> 2);
        int cc = n0 + nt2*8 + (lane & 3)*2;
        size_t base = (size_t)(z0 + r)*6144 + (size_t)pi*128 + cc;
        *(__half2*)(g_S + base) = __floats2half2_rn(acc[mt][nt2][0], acc[mt][nt2][1]);
        *(__half2*)(g_S + base + 8*6144) = __floats2half2_rn(acc[mt][nt2][2], acc[mt][nt2][3]);
      }
    __syncthreads();
  }
  #undef ISSUE_A
}

// ---------------- step2: out_z = S_z[128x48] @ M_z^T ----------------
// per-warp: S 48 rows x 256B swizzled = 12288; M 16x112B = 1792.
// smem = 4*12288 + 4*1792 = 56320 -> 4 CTAs/SM.
__global__ void __launch_bounds__(128) step2(float* __restrict__ out){
  extern __shared__ __align__(1024) char smem[];
  uint32_t sb = smem_u32(smem);
  int tid = threadIdx.x, wid = tid >> 5, lane = tid & 31;

  const int WSTR = 12288;
  const int OFF_M = 49152;
  int z0 = blockIdx.x * 4;
  size_t z = z0 + wid;
  uint32_t sbS = sb + wid*WSTR;
  uint32_t sbM = sb + OFF_M + wid*1792;

  // zero pad rows 43..47 first (full 256B rows; disjoint from cp.async rows 0-42)
  for (int t = lane; t < 160; t += 32){
    int row = 43 + t/32, col = t & 31;
    asm volatile("st.shared.u64 [%0], %1;" :: "r"(sbS + row*256 + col*8), "l"(0ull));
  }

  // group a: M + S rows 0-15
  for (int t = lane; t < 112; t += 32)
    cp16(sbM + t*16, g_M + z*896 + t*8);
  for (int t = lane; t < 256; t += 32){
    int row = t >> 4, c16 = t & 15;
    cp16(sbS + SWZ2(row, c16), g_S + z*6144 + row*128 + c16*8);
  }
  cp_commit();
  // group b: S rows 16-31
  for (int t = lane; t < 256; t += 32){
    int row = 16 + (t >> 4), c16 = t & 15;
    cp16(sbS + SWZ2(row, c16), g_S + z*6144 + row*128 + c16*8);
  }
  cp_commit();
  // group c: S rows 32-42
  for (int t = lane; t < 176; t += 32){
    int row = 32 + (t >> 4), c16 = t & 15;
    cp16(sbS + SWZ2(row, c16), g_S + z*6144 + row*128 + c16*8);
  }
  cp_commit();

  float acc[8][2][4];
  #pragma unroll
  for (int a = 0; a < 8; ++a)
    #pragma unroll
    for (int b = 0; b < 2; ++b)
      #pragma unroll
      for (int c = 0; c < 4; ++c) acc[a][b][c] = 0.f;

  int r4 = lane >> 2, c2 = (lane & 3)*2;
  int nrow = (lane & 7) + ((lane >> 4) << 3);
  int bcol = ((lane >> 3) & 1) * 16;
  int tRow = (lane & 7) + ((lane >> 4) & 1) * 8;
  int tBlk = (lane >> 3) & 1;   // 16B block within the mt pair

  cp_wait<2>();
  __syncwarp();

  #pragma unroll
  for (int kt = 0; kt < 3; ++kt){
    if (kt == 1){ cp_wait<1>(); __syncwarp(); }
    if (kt == 2){ cp_wait<0>(); __syncwarp(); }
    uint32_t bfr[4];
    ldsm4(bfr, sbM + nrow*112 + kt*32 + bcol);
    int row = kt*16 + tRow;
    #pragma unroll
    for (int mt = 0; mt < 8; ++mt){
      uint32_t a[4];
      ldsm4t(a, sbS + SWZ2(row, mt*2 + tBlk));   // rows 43-47 zeroed
      mma16816(acc[mt][0], a, bfr[0], bfr[1]);
      mma16816(acc[mt][1], a, bfr[2], bfr[3]);
    }
  }
  __syncwarp();

  // stage out tile [128][18] f32 in S region (9216B < 12288B)
  #pragma unroll
  for (int mt = 0; mt < 8; ++mt)
    #pragma unroll
    for (int nt = 0; nt < 2; ++nt){
      int m = mt*16 + r4;
      int cc = nt*8 + c2;
      asm volatile("st.shared.v2.f32 [%0], {%1,%2};"
        :: "r"(sbS + (m*18 + cc)*4), "f"(acc[mt][nt][0]), "f"(acc[mt][nt][1]) : "memory");
      asm volatile("st.shared.v2.f32 [%0], {%1,%2};"
        :: "r"(sbS + ((m+8)*18 + cc)*4), "f"(acc[mt][nt][2]), "f"(acc[mt][nt][3]) : "memory");
    }
  __syncwarp();

  const float* Osh = (const float*)(smem + wid*WSTR);
  size_t ob = z * 1152;
  #pragma unroll
  for (int j = 0; j < 9; ++j){
    int o = (lane + j*32) * 4;
    unsigned long long mv = __ldg((const unsigned long long*)(g_map + o));
    float4 v;
    v.x = Osh[(int)(mv & 0xffff)];
    v.y = Osh[(int)((mv >> 16) & 0xffff)];
    v.z = Osh[(int)((mv >> 32) & 0xffff)];
    v.w = Osh[(int)((mv >> 48) & 0xffff)];
    *(float4*)(out + ob + o) = v;
  }
}

// ---------------- launch ----------------
extern "C" void kernel_launch(void* const* d_in, const int* in_sizes, int n_in,
                              void* d_out, int out_size){
  const float* x = (const float*)d_in[0];
  const float* y = (const float*)d_in[1];
  const float* w = (const float*)d_in[2];
  float* out = (float*)d_out;
  int n = in_sizes[0] / 1152;   // 65536

  cudaFuncSetAttribute(gemm1, cudaFuncAttributeMaxDynamicSharedMemorySize, SMEM_G1);
  cudaFuncSetAttribute(step2, cudaFuncAttributeMaxDynamicSharedMemorySize, SMEM_S2);

  cg_kernel<<<1, 32>>>();
  wprep<<<(1664*128 + 255)/256, 256>>>(w);
  xprep<<<n / 4, 256>>>(x);
  mprep<<<n / 32, 256>>>(y);
  gemm1<<<64 * 43, 256, SMEM_G1>>>();
  step2<<<n / 4, 128, SMEM_S2>>>(out);
}